// round 4
// baseline (speedup 1.0000x reference)
#include <cuda_runtime.h>
#include <cuda_bf16.h>
#include <cstdint>

#define NN 50000
#define EE 800000
#define HH 128
#define GG 256
#define SCHUNK 512
#define MAXNB 128   // >= ceil(NN/SCHUNK)=98

// ---------------- scratch (device globals: no allocation allowed) -----------
__device__ float g_zw[NN * HH];     // z @ W result
__device__ float g_z1[NN * HH];     // layer-1 activation
__device__ float g_dinv[NN];        // 1/sqrt(deg)
__device__ int   g_cnt[NN];         // degree histogram (INVARIANT: 0 at launch entry)
__device__ int   g_cur[NN];         // fill cursor (= rowptr at fill start)
__device__ int   g_rowptr[NN + 1];  // CSR row pointers (by dst)
__device__ int   g_col[EE];         // CSR column (src) indices
__device__ int   g_bsum[MAXNB];     // per-chunk sums
// stage-completion counters (INVARIANT: 0 at launch entry; reset by gather0)
__device__ int   g_done_count;
__device__ int   g_done_reduce;
__device__ int   g_done_scan;

// ---------------- TF32 helpers -------------------------------------------------
__device__ __forceinline__ uint32_t f2tf32(float x) {
    uint32_t y;
    asm("cvt.rna.tf32.f32 %0, %1;" : "=r"(y) : "f"(x));
    return y;
}

__device__ __forceinline__ void mma_tf32(float c[4],
                                         uint32_t a0, uint32_t a1,
                                         uint32_t a2, uint32_t a3,
                                         uint32_t b0, uint32_t b1) {
    asm volatile(
        "mma.sync.aligned.m16n8k8.row.col.f32.tf32.tf32.f32 "
        "{%0,%1,%2,%3}, {%4,%5,%6,%7}, {%8,%9}, {%0,%1,%2,%3};"
        : "+f"(c[0]), "+f"(c[1]), "+f"(c[2]), "+f"(c[3])
        : "r"(a0), "r"(a1), "r"(a2), "r"(a3), "r"(b0), "r"(b1));
}

// ---------------- 3xTF32 GEMM body: 128x128 tile, 256 threads ------------------
__device__ __forceinline__ void gemm_body(
    float (*As)[36], float (*Bs)[136],
    const float* __restrict__ A, const float* __restrict__ W,
    float* __restrict__ C, int n, int m0) {
    int tid = threadIdx.x;
    int lane = tid & 31, wid = tid >> 5;
    int wm = wid >> 1;
    int wn = wid & 1;

    float acc[2][8][4];
    #pragma unroll
    for (int ms = 0; ms < 2; ms++)
        #pragma unroll
        for (int nt = 0; nt < 8; nt++)
            #pragma unroll
            for (int j = 0; j < 4; j++) acc[ms][nt][j] = 0.0f;

    int kq = lane & 3;
    int rq = lane >> 2;

    for (int k0 = 0; k0 < 128; k0 += 32) {
        #pragma unroll
        for (int it = 0; it < 4; it++) {
            int f = tid + 256 * it;
            int row = f >> 3;
            int k4 = (f & 7) * 4;
            int rg = m0 + row;
            if (rg >= n) rg = n - 1;
            float4 a = *(const float4*)&A[(size_t)rg * 128 + k0 + k4];
            *(float4*)&As[row][k4] = a;
        }
        #pragma unroll
        for (int it = 0; it < 4; it++) {
            int f = tid + 256 * it;
            int k = f >> 5;
            int nc = (f & 31) * 4;
            float4 b = *(const float4*)&W[(size_t)(k0 + k) * 128 + nc];
            *(float4*)&Bs[k][nc] = b;
        }
        __syncthreads();

        #pragma unroll
        for (int kk = 0; kk < 32; kk += 8) {
            // A fragments for BOTH ms subtiles (cvt once)
            uint32_t ah[2][4], al[2][4];
            #pragma unroll
            for (int ms = 0; ms < 2; ms++) {
                int r = wm * 32 + ms * 16 + rq;
                float af0 = As[r][kk + kq];
                float af1 = As[r + 8][kk + kq];
                float af2 = As[r][kk + kq + 4];
                float af3 = As[r + 8][kk + kq + 4];
                ah[ms][0] = f2tf32(af0); ah[ms][1] = f2tf32(af1);
                ah[ms][2] = f2tf32(af2); ah[ms][3] = f2tf32(af3);
                al[ms][0] = f2tf32(af0 - __uint_as_float(ah[ms][0]));
                al[ms][1] = f2tf32(af1 - __uint_as_float(ah[ms][1]));
                al[ms][2] = f2tf32(af2 - __uint_as_float(ah[ms][2]));
                al[ms][3] = f2tf32(af3 - __uint_as_float(ah[ms][3]));
            }
            #pragma unroll
            for (int nt = 0; nt < 8; nt++) {
                int nc = wn * 64 + nt * 8 + rq;
                float bf0 = Bs[kk + kq][nc];
                float bf1 = Bs[kk + kq + 4][nc];
                uint32_t bh0 = f2tf32(bf0), bh1 = f2tf32(bf1);
                uint32_t bl0 = f2tf32(bf0 - __uint_as_float(bh0));
                uint32_t bl1 = f2tf32(bf1 - __uint_as_float(bh1));
                #pragma unroll
                for (int ms = 0; ms < 2; ms++) {
                    mma_tf32(acc[ms][nt], al[ms][0], al[ms][1], al[ms][2], al[ms][3], bh0, bh1);
                    mma_tf32(acc[ms][nt], ah[ms][0], ah[ms][1], ah[ms][2], ah[ms][3], bl0, bl1);
                    mma_tf32(acc[ms][nt], ah[ms][0], ah[ms][1], ah[ms][2], ah[ms][3], bh0, bh1);
                }
            }
        }
        __syncthreads();
    }

    #pragma unroll
    for (int ms = 0; ms < 2; ms++) {
        int r0 = m0 + wm * 32 + ms * 16 + rq;
        #pragma unroll
        for (int nt = 0; nt < 8; nt++) {
            int nc = wn * 64 + nt * 8 + (lane & 3) * 2;
            if (r0 < n) {
                float2 v = {acc[ms][nt][0], acc[ms][nt][1]};
                *(float2*)&C[(size_t)r0 * 128 + nc] = v;
            }
            if (r0 + 8 < n) {
                float2 v = {acc[ms][nt][2], acc[ms][nt][3]};
                *(float2*)&C[(size_t)(r0 + 8) * 128 + nc] = v;
            }
        }
    }
}

// ---------------- stage wait helper --------------------------------------------
__device__ __forceinline__ void wait_counter(int* ctr, int target) {
    if (threadIdx.x == 0) {
        while (*(volatile int*)ctr < target) __nanosleep(128);
    }
    __syncthreads();
    __threadfence();
}

__device__ __forceinline__ void publish_counter(int* ctr) {
    __syncthreads();
    if (threadIdx.x == 0) {
        __threadfence();
        atomicAdd(ctr, 1);
    }
}

// ---------------- MEGA kernel: gemm0 | count+zero -> reduce -> scan -> fill ----
// Block roles by blockIdx.x range. Later stages spin on counters published by
// earlier stages; waiting blocks depend only on lower block IDs (dispatch order
// guarantees forward progress).
__global__ void __launch_bounds__(256) mega_kernel(
    const int* __restrict__ src, const int* __restrict__ dst, int e,
    float* __restrict__ pool, int gsize,
    const float* __restrict__ A, const float* __restrict__ W,
    float* __restrict__ C, int n,
    int GB, int CB, int RB, int FB) {
    __shared__ float As[128][36];
    __shared__ float Bs[32][136];
    int b = blockIdx.x;
    int tid = threadIdx.x;

    if (b < GB) {
        // ---- GEMM layer 0 (independent of everything) ----
        gemm_body(As, Bs, A, W, C, n, b * 128);
        return;
    }
    b -= GB;
    if (b < CB) {
        // ---- degree count (+ pool zeroing in the first blocks) ----
        int i = b * 256 + tid;
        if (i < e) atomicAdd(&g_cnt[dst[i]], 1);
        if (i < gsize) pool[i] = 0.0f;
        publish_counter(&g_done_count);
        return;
    }
    b -= CB;
    if (b < RB) {
        // ---- per-chunk reduce ----
        wait_counter(&g_done_count, CB);
        __shared__ int ws[8];
        int lane = tid & 31, wid = tid >> 5;
        int i = b * SCHUNK + tid * 2;
        int s = (i < n ? g_cnt[i] : 0) + (i + 1 < n ? g_cnt[i + 1] : 0);
        #pragma unroll
        for (int d = 16; d > 0; d >>= 1) s += __shfl_down_sync(0xFFFFFFFFu, s, d);
        if (lane == 0) ws[wid] = s;
        __syncthreads();
        if (tid == 0) {
            int t = 0;
            #pragma unroll
            for (int w = 0; w < 8; w++) t += ws[w];
            g_bsum[b] = t;
        }
        publish_counter(&g_done_reduce);
        return;
    }
    b -= RB;
    if (b < RB) {
        // ---- per-chunk scan + write rowptr/dinv/cur (chunk offset computed locally) ----
        wait_counter(&g_done_reduce, RB);
        __shared__ int ws[8];
        __shared__ int sadd;
        int lane = tid & 31, wid = tid >> 5;
        // local prefix over chunk sums [0, b)
        if (tid == 0) sadd = 0;
        __syncthreads();
        int part = 0;
        for (int j = tid; j < b; j += 256) part += g_bsum[j];
        #pragma unroll
        for (int d = 16; d > 0; d >>= 1) part += __shfl_down_sync(0xFFFFFFFFu, part, d);
        if (lane == 0 && part != 0) atomicAdd(&sadd, part);
        __syncthreads();

        int base = b * SCHUNK + tid * 2;
        int v0 = base < n ? g_cnt[base] : 0;
        int v1 = base + 1 < n ? g_cnt[base + 1] : 0;
        int t = v0 + v1;
        int x = t;
        #pragma unroll
        for (int d = 1; d < 32; d <<= 1) {
            int y = __shfl_up_sync(0xFFFFFFFFu, x, d);
            if (lane >= d) x += y;
        }
        if (lane == 31) ws[wid] = x;
        __syncthreads();
        int add = sadd;
        for (int w = 0; w < wid; w++) add += ws[w];
        int excl = x - t + add;
        if (base < n) {
            g_rowptr[base + 1] = excl + v0;
            g_cur[base] = excl;
            g_dinv[base] = rsqrtf((float)(v0 + 1));  // +1 self loop
            g_cnt[base] = 0;                         // restore invariant
        }
        if (base + 1 < n) {
            g_rowptr[base + 2] = excl + v0 + v1;
            g_cur[base + 1] = excl + v0;
            g_dinv[base + 1] = rsqrtf((float)(v1 + 1));
            g_cnt[base + 1] = 0;
        }
        if (b == 0 && tid == 0) g_rowptr[0] = 0;
        publish_counter(&g_done_scan);
        return;
    }
    b -= RB;
    // ---- CSR fill ----
    wait_counter(&g_done_scan, RB);
    int i = b * 256 + tid;
    if (i < e) {
        int pos = atomicAdd(&g_cur[dst[i]], 1);
        g_col[pos] = src[i];
    }
}

// ---------------- plain GEMM kernel (layer 1) ----------------------------------
__global__ void __launch_bounds__(256) gemm_tf32_kernel(
    const float* __restrict__ A, const float* __restrict__ W,
    float* __restrict__ C, int n) {
    __shared__ float As[128][36];
    __shared__ float Bs[32][136];
    gemm_body(As, Bs, A, W, C, n, blockIdx.x * 128);
}

// ---------------- gather + bias + PReLU + pooled reduction --------------------
__global__ void __launch_bounds__(256) gather_kernel(
    const float* __restrict__ zw,
    const float* __restrict__ bias,
    const float* __restrict__ alpha,
    const int* __restrict__ batch,
    float* __restrict__ zout,
    float* __restrict__ pool,
    int n, int reset) {
    __shared__ float sred[8][132];
    __shared__ int sgi[8];
    if (reset && blockIdx.x == 0 && threadIdx.x == 0) {
        g_done_count = 0;
        g_done_reduce = 0;
        g_done_scan = 0;
    }
    int wid = threadIdx.x >> 5, lane = threadIdx.x & 31;
    int i = blockIdx.x * 8 + wid;
    bool valid = i < n;

    float z0 = 0.f, z1 = 0.f, z2 = 0.f, z3 = 0.f;
    int gi = -1;

    if (valid) {
        const float4* __restrict__ zwv = (const float4*)zw;
        float di = g_dinv[i];
        float4 v = zwv[(size_t)i * 32 + lane];
        float4 acc;
        acc.x = di * v.x; acc.y = di * v.y; acc.z = di * v.z; acc.w = di * v.w;

        int e0 = g_rowptr[i], e1 = g_rowptr[i + 1];
        int e = e0;
        for (; e + 4 <= e1; e += 4) {
            int s0 = g_col[e + 0];
            int s1 = g_col[e + 1];
            int s2 = g_col[e + 2];
            int s3 = g_col[e + 3];
            float4 u0 = zwv[(size_t)s0 * 32 + lane];
            float4 u1 = zwv[(size_t)s1 * 32 + lane];
            float4 u2 = zwv[(size_t)s2 * 32 + lane];
            float4 u3 = zwv[(size_t)s3 * 32 + lane];
            float d0 = g_dinv[s0], d1 = g_dinv[s1];
            float d2 = g_dinv[s2], d3 = g_dinv[s3];
            acc.x = fmaf(d0, u0.x, fmaf(d1, u1.x, fmaf(d2, u2.x, fmaf(d3, u3.x, acc.x))));
            acc.y = fmaf(d0, u0.y, fmaf(d1, u1.y, fmaf(d2, u2.y, fmaf(d3, u3.y, acc.y))));
            acc.z = fmaf(d0, u0.z, fmaf(d1, u1.z, fmaf(d2, u2.z, fmaf(d3, u3.z, acc.z))));
            acc.w = fmaf(d0, u0.w, fmaf(d1, u1.w, fmaf(d2, u2.w, fmaf(d3, u3.w, acc.w))));
        }
        for (; e < e1; e++) {
            int s = g_col[e];
            float ds = g_dinv[s];
            float4 u = zwv[(size_t)s * 32 + lane];
            acc.x = fmaf(ds, u.x, acc.x);
            acc.y = fmaf(ds, u.y, acc.y);
            acc.z = fmaf(ds, u.z, acc.z);
            acc.w = fmaf(ds, u.w, acc.w);
        }

        float4 b  = ((const float4*)bias)[lane];
        float4 al = ((const float4*)alpha)[lane];
        z0 = fmaf(acc.x, di, b.x);
        z1 = fmaf(acc.y, di, b.y);
        z2 = fmaf(acc.z, di, b.z);
        z3 = fmaf(acc.w, di, b.w);
        z0 = z0 > 0.0f ? z0 : al.x * z0;
        z1 = z1 > 0.0f ? z1 : al.y * z1;
        z2 = z2 > 0.0f ? z2 : al.z * z2;
        z3 = z3 > 0.0f ? z3 : al.w * z3;

        float4 out = {z0, z1, z2, z3};
        ((float4*)zout)[(size_t)i * 32 + lane] = out;
        gi = batch[i];
    }

    if (lane == 0) sgi[wid] = gi;
    sred[wid][lane * 4 + 0] = z0;
    sred[wid][lane * 4 + 1] = z1;
    sred[wid][lane * 4 + 2] = z2;
    sred[wid][lane * 4 + 3] = z3;
    __syncthreads();

    int g0 = sgi[0];
    bool uni = (g0 >= 0);
    #pragma unroll
    for (int w = 1; w < 8; w++) uni = uni && (sgi[w] == g0);

    if (uni) {
        int f = threadIdx.x;
        if (f < 128) {
            float s = 0.f;
            #pragma unroll
            for (int w = 0; w < 8; w++) s += sred[w][f];
            atomicAdd(&pool[(size_t)g0 * 256 + f], s);
        }
    } else if (valid) {
        float* p = &pool[(size_t)gi * 256 + lane * 4];
        atomicAdd(p + 0, z0);
        atomicAdd(p + 1, z1);
        atomicAdd(p + 2, z2);
        atomicAdd(p + 3, z3);
    }
}

// ---------------- launch -------------------------------------------------------
extern "C" void kernel_launch(void* const* d_in, const int* in_sizes, int n_in,
                              void* d_out, int out_size) {
    const float* x      = (const float*)d_in[0];
    const int*   eidx   = (const int*)d_in[1];
    const int*   batch  = (const int*)d_in[2];
    const float* W0     = (const float*)d_in[3];
    const float* b0     = (const float*)d_in[4];
    const float* alpha0 = (const float*)d_in[5];
    const float* W1     = (const float*)d_in[6];
    const float* b1     = (const float*)d_in[7];
    const float* alpha1 = (const float*)d_in[8];

    int n = in_sizes[0] / HH;       // 50000
    int e = in_sizes[1] / 2;        // 800000
    const int* src = eidx;
    const int* dst = eidx + e;

    float* z2_out = (float*)d_out;                   // [n,128]
    float* g_pool = (float*)d_out + (size_t)n * HH;  // [G, 256]
    int gsize = out_size - n * HH;                   // 65536

    float* zw;  cudaGetSymbolAddress((void**)&zw, g_zw);
    float* z1;  cudaGetSymbolAddress((void**)&z1, g_z1);

    int GB = (n + 127) / 128;            // gemm blocks  (391)
    int CB = (e + 255) / 256;            // count blocks (3125)
    int RB = (n + SCHUNK - 1) / SCHUNK;  // reduce/scan blocks (98)
    int FB = CB;                         // fill blocks
    int gather_blocks = (n + 7) / 8;

    // Front end: GEMM0 runs concurrently with count -> reduce -> scan -> fill
    mega_kernel<<<GB + CB + RB + RB + FB, 256>>>(
        src, dst, e, g_pool, gsize, x, W0, zw, n, GB, CB, RB, FB);

    // Layer 0 aggregate (also resets stage counters for the next launch)
    gather_kernel<<<gather_blocks, 256>>>(zw, b0, alpha0, batch, z1, g_pool, n, 1);
    // Layer 1
    gemm_tf32_kernel<<<GB, 256>>>(z1, W1, zw, n);
    gather_kernel<<<gather_blocks, 256>>>(zw, b1, alpha1, batch, z2_out,
                                          g_pool + HH, n, 0);
}

// round 5
// speedup vs baseline: 1.3734x; 1.3734x over previous
#include <cuda_runtime.h>
#include <cuda_fp16.h>
#include <cstdint>

#define NN 50000
#define EE 800000
#define HH 128
#define GG 256
#define SCHUNK 512
#define MAXNB 128   // >= ceil(NN/SCHUNK)=98

// ---------------- scratch (device globals: no allocation allowed) -----------
__device__ __half g_zwh[NN * HH];   // z @ W result (fp16 for gather bandwidth)
__device__ float g_z1[NN * HH];     // layer-1 activation (fp32)
__device__ float g_dinv[NN];        // 1/sqrt(deg)
__device__ int   g_cnt[NN];         // degree histogram (INVARIANT: 0 at launch entry)
__device__ int   g_cur[NN];         // fill cursor
__device__ int   g_rowptr[NN + 1];  // CSR row pointers (by dst)
__device__ int   g_col[EE];         // CSR column (src) indices
__device__ int   g_bsum[MAXNB];     // per-chunk sums

// ---------------- TF32 helpers -------------------------------------------------
__device__ __forceinline__ uint32_t f2tf32(float x) {
    uint32_t y;
    asm("cvt.rna.tf32.f32 %0, %1;" : "=r"(y) : "f"(x));
    return y;
}

__device__ __forceinline__ void mma_tf32(float c[4],
                                         uint32_t a0, uint32_t a1,
                                         uint32_t a2, uint32_t a3,
                                         uint32_t b0, uint32_t b1) {
    asm volatile(
        "mma.sync.aligned.m16n8k8.row.col.f32.tf32.tf32.f32 "
        "{%0,%1,%2,%3}, {%4,%5,%6,%7}, {%8,%9}, {%0,%1,%2,%3};"
        : "+f"(c[0]), "+f"(c[1]), "+f"(c[2]), "+f"(c[3])
        : "r"(a0), "r"(a1), "r"(a2), "r"(a3), "r"(b0), "r"(b1));
}

// ---------------- 3xTF32 GEMM body: 128x128 tile, fp16 output ------------------
__device__ __forceinline__ void gemm_body(
    float (*As)[36], float (*Bs)[136],
    const float* __restrict__ A, const float* __restrict__ W,
    __half* __restrict__ C, int n, int m0) {
    int tid = threadIdx.x;
    int lane = tid & 31, wid = tid >> 5;
    int wm = wid >> 1;
    int wn = wid & 1;

    float acc[2][8][4];
    #pragma unroll
    for (int ms = 0; ms < 2; ms++)
        #pragma unroll
        for (int nt = 0; nt < 8; nt++)
            #pragma unroll
            for (int j = 0; j < 4; j++) acc[ms][nt][j] = 0.0f;

    int kq = lane & 3;
    int rq = lane >> 2;

    for (int k0 = 0; k0 < 128; k0 += 32) {
        #pragma unroll
        for (int it = 0; it < 4; it++) {
            int f = tid + 256 * it;
            int row = f >> 3;
            int k4 = (f & 7) * 4;
            int rg = m0 + row;
            if (rg >= n) rg = n - 1;
            float4 a = *(const float4*)&A[(size_t)rg * 128 + k0 + k4];
            *(float4*)&As[row][k4] = a;
        }
        #pragma unroll
        for (int it = 0; it < 4; it++) {
            int f = tid + 256 * it;
            int k = f >> 5;
            int nc = (f & 31) * 4;
            float4 b = *(const float4*)&W[(size_t)(k0 + k) * 128 + nc];
            *(float4*)&Bs[k][nc] = b;
        }
        __syncthreads();

        #pragma unroll
        for (int kk = 0; kk < 32; kk += 8) {
            uint32_t ah[2][4], al[2][4];
            #pragma unroll
            for (int ms = 0; ms < 2; ms++) {
                int r = wm * 32 + ms * 16 + rq;
                float af0 = As[r][kk + kq];
                float af1 = As[r + 8][kk + kq];
                float af2 = As[r][kk + kq + 4];
                float af3 = As[r + 8][kk + kq + 4];
                ah[ms][0] = f2tf32(af0); ah[ms][1] = f2tf32(af1);
                ah[ms][2] = f2tf32(af2); ah[ms][3] = f2tf32(af3);
                al[ms][0] = f2tf32(af0 - __uint_as_float(ah[ms][0]));
                al[ms][1] = f2tf32(af1 - __uint_as_float(ah[ms][1]));
                al[ms][2] = f2tf32(af2 - __uint_as_float(ah[ms][2]));
                al[ms][3] = f2tf32(af3 - __uint_as_float(ah[ms][3]));
            }
            #pragma unroll
            for (int nt = 0; nt < 8; nt++) {
                int nc = wn * 64 + nt * 8 + rq;
                float bf0 = Bs[kk + kq][nc];
                float bf1 = Bs[kk + kq + 4][nc];
                uint32_t bh0 = f2tf32(bf0), bh1 = f2tf32(bf1);
                uint32_t bl0 = f2tf32(bf0 - __uint_as_float(bh0));
                uint32_t bl1 = f2tf32(bf1 - __uint_as_float(bh1));
                #pragma unroll
                for (int ms = 0; ms < 2; ms++) {
                    mma_tf32(acc[ms][nt], al[ms][0], al[ms][1], al[ms][2], al[ms][3], bh0, bh1);
                    mma_tf32(acc[ms][nt], ah[ms][0], ah[ms][1], ah[ms][2], ah[ms][3], bl0, bl1);
                    mma_tf32(acc[ms][nt], ah[ms][0], ah[ms][1], ah[ms][2], ah[ms][3], bh0, bh1);
                }
            }
        }
        __syncthreads();
    }

    // epilogue: convert to fp16, write __half2 per (ms,nt)
    __half2* Ch = (__half2*)C;
    #pragma unroll
    for (int ms = 0; ms < 2; ms++) {
        int r0 = m0 + wm * 32 + ms * 16 + rq;
        #pragma unroll
        for (int nt = 0; nt < 8; nt++) {
            int nc = wn * 64 + nt * 8 + (lane & 3) * 2;
            if (r0 < n)
                Ch[(size_t)r0 * 64 + (nc >> 1)] =
                    __floats2half2_rn(acc[ms][nt][0], acc[ms][nt][1]);
            if (r0 + 8 < n)
                Ch[(size_t)(r0 + 8) * 64 + (nc >> 1)] =
                    __floats2half2_rn(acc[ms][nt][2], acc[ms][nt][3]);
        }
    }
}

// ---------------- fused: count | pool-zero | GEMM0 ----------------------------
__global__ void __launch_bounds__(256) fusedA_kernel(
    const int* __restrict__ dst, int e,
    float* __restrict__ pool, int gsize,
    const float* __restrict__ A, const float* __restrict__ W,
    __half* __restrict__ C, int n, int count_blocks, int zero_blocks) {
    __shared__ float As[128][36];
    __shared__ float Bs[32][136];
    int b = blockIdx.x;
    if (b < count_blocks) {
        int i = b * 256 + threadIdx.x;
        if (i < e) atomicAdd(&g_cnt[dst[i]], 1);
    } else if (b < count_blocks + zero_blocks) {
        int i = (b - count_blocks) * 256 + threadIdx.x;
        if (i < gsize) pool[i] = 0.0f;
    } else {
        gemm_body(As, Bs, A, W, C, n, (b - count_blocks - zero_blocks) * 128);
    }
}

// ---------------- plain GEMM kernel (layer 1) ----------------------------------
__global__ void __launch_bounds__(256) gemm_tf32_kernel(
    const float* __restrict__ A, const float* __restrict__ W,
    __half* __restrict__ C, int n) {
    __shared__ float As[128][36];
    __shared__ float Bs[32][136];
    gemm_body(As, Bs, A, W, C, n, blockIdx.x * 128);
}

// ---------------- scan phase 1: per-chunk reduce ------------------------------
__global__ void __launch_bounds__(256) reduce_kernel(int n) {
    __shared__ int ws[8];
    int b = blockIdx.x, tid = threadIdx.x;
    int lane = tid & 31, wid = tid >> 5;
    int i = b * SCHUNK + tid * 2;
    int s = (i < n ? g_cnt[i] : 0) + (i + 1 < n ? g_cnt[i + 1] : 0);
    #pragma unroll
    for (int d = 16; d > 0; d >>= 1) s += __shfl_down_sync(0xFFFFFFFFu, s, d);
    if (lane == 0) ws[wid] = s;
    __syncthreads();
    if (tid == 0) {
        int t = 0;
        #pragma unroll
        for (int w = 0; w < 8; w++) t += ws[w];
        g_bsum[b] = t;
    }
}

// ---------------- scan phase 2 (merged): chunk-offset + scan + write ----------
__global__ void __launch_bounds__(256) scan_write_kernel(int n) {
    __shared__ int ws[8];
    __shared__ int sadd;
    int b = blockIdx.x, tid = threadIdx.x;
    int lane = tid & 31, wid = tid >> 5;

    if (tid == 0) sadd = 0;
    __syncthreads();
    int part = 0;
    for (int j = tid; j < b; j += 256) part += g_bsum[j];
    #pragma unroll
    for (int d = 16; d > 0; d >>= 1) part += __shfl_down_sync(0xFFFFFFFFu, part, d);
    if (lane == 0 && part != 0) atomicAdd(&sadd, part);
    __syncthreads();

    int base = b * SCHUNK + tid * 2;
    int v0 = base < n ? g_cnt[base] : 0;
    int v1 = base + 1 < n ? g_cnt[base + 1] : 0;
    int t = v0 + v1;
    int x = t;
    #pragma unroll
    for (int d = 1; d < 32; d <<= 1) {
        int y = __shfl_up_sync(0xFFFFFFFFu, x, d);
        if (lane >= d) x += y;
    }
    if (lane == 31) ws[wid] = x;
    __syncthreads();
    int add = sadd;
    for (int w = 0; w < wid; w++) add += ws[w];
    int excl = x - t + add;
    if (base < n) {
        g_rowptr[base + 1] = excl + v0;
        g_cur[base] = excl;
        g_dinv[base] = rsqrtf((float)(v0 + 1));  // +1 self loop
        g_cnt[base] = 0;                         // restore invariant
    }
    if (base + 1 < n) {
        g_rowptr[base + 2] = excl + v0 + v1;
        g_cur[base + 1] = excl + v0;
        g_dinv[base + 1] = rsqrtf((float)(v1 + 1));
        g_cnt[base + 1] = 0;
    }
    if (b == 0 && tid == 0) g_rowptr[0] = 0;
}

// ---------------- CSR fill ----------------------------------------------------
__global__ void fill_kernel(const int* __restrict__ src,
                            const int* __restrict__ dst, int e) {
    int i = blockIdx.x * blockDim.x + threadIdx.x;
    if (i < e) {
        int pos = atomicAdd(&g_cur[dst[i]], 1);
        g_col[pos] = src[i];
    }
}

// ---------------- gather (fp16 in) + bias + PReLU + pooled reduction ----------
__global__ void __launch_bounds__(256) gather_kernel(
    const __half* __restrict__ zwh,
    const float* __restrict__ bias,
    const float* __restrict__ alpha,
    const int* __restrict__ batch,
    float* __restrict__ zout,
    float* __restrict__ pool,
    int n) {
    __shared__ float sred[8][132];
    __shared__ int sgi[8];
    int wid = threadIdx.x >> 5, lane = threadIdx.x & 31;
    int i = blockIdx.x * 8 + wid;
    bool valid = i < n;

    float z0 = 0.f, z1 = 0.f, z2 = 0.f, z3 = 0.f;
    int gi = -1;

    if (valid) {
        const uint2* __restrict__ zwv = (const uint2*)zwh;  // 4 halves per lane
        float di = g_dinv[i];

        uint2 sv = zwv[(size_t)i * 32 + lane];
        float2 f0 = __half22float2(*(const __half2*)&sv.x);
        float2 f1 = __half22float2(*(const __half2*)&sv.y);
        float4 acc;
        acc.x = di * f0.x; acc.y = di * f0.y;
        acc.z = di * f1.x; acc.w = di * f1.y;

        int e0 = g_rowptr[i], e1 = g_rowptr[i + 1];
        int e = e0;
        for (; e + 4 <= e1; e += 4) {
            int s0 = g_col[e + 0];
            int s1 = g_col[e + 1];
            int s2 = g_col[e + 2];
            int s3 = g_col[e + 3];
            uint2 u0 = zwv[(size_t)s0 * 32 + lane];
            uint2 u1 = zwv[(size_t)s1 * 32 + lane];
            uint2 u2 = zwv[(size_t)s2 * 32 + lane];
            uint2 u3 = zwv[(size_t)s3 * 32 + lane];
            float d0 = g_dinv[s0], d1 = g_dinv[s1];
            float d2 = g_dinv[s2], d3 = g_dinv[s3];
            float2 a0 = __half22float2(*(const __half2*)&u0.x);
            float2 b0 = __half22float2(*(const __half2*)&u0.y);
            float2 a1 = __half22float2(*(const __half2*)&u1.x);
            float2 b1 = __half22float2(*(const __half2*)&u1.y);
            float2 a2 = __half22float2(*(const __half2*)&u2.x);
            float2 b2 = __half22float2(*(const __half2*)&u2.y);
            float2 a3 = __half22float2(*(const __half2*)&u3.x);
            float2 b3 = __half22float2(*(const __half2*)&u3.y);
            acc.x = fmaf(d0, a0.x, fmaf(d1, a1.x, fmaf(d2, a2.x, fmaf(d3, a3.x, acc.x))));
            acc.y = fmaf(d0, a0.y, fmaf(d1, a1.y, fmaf(d2, a2.y, fmaf(d3, a3.y, acc.y))));
            acc.z = fmaf(d0, b0.x, fmaf(d1, b1.x, fmaf(d2, b2.x, fmaf(d3, b3.x, acc.z))));
            acc.w = fmaf(d0, b0.y, fmaf(d1, b1.y, fmaf(d2, b2.y, fmaf(d3, b3.y, acc.w))));
        }
        for (; e < e1; e++) {
            int s = g_col[e];
            float ds = g_dinv[s];
            uint2 u = zwv[(size_t)s * 32 + lane];
            float2 a = __half22float2(*(const __half2*)&u.x);
            float2 c = __half22float2(*(const __half2*)&u.y);
            acc.x = fmaf(ds, a.x, acc.x);
            acc.y = fmaf(ds, a.y, acc.y);
            acc.z = fmaf(ds, c.x, acc.z);
            acc.w = fmaf(ds, c.y, acc.w);
        }

        float4 b  = ((const float4*)bias)[lane];
        float4 al = ((const float4*)alpha)[lane];
        z0 = fmaf(acc.x, di, b.x);
        z1 = fmaf(acc.y, di, b.y);
        z2 = fmaf(acc.z, di, b.z);
        z3 = fmaf(acc.w, di, b.w);
        z0 = z0 > 0.0f ? z0 : al.x * z0;
        z1 = z1 > 0.0f ? z1 : al.y * z1;
        z2 = z2 > 0.0f ? z2 : al.z * z2;
        z3 = z3 > 0.0f ? z3 : al.w * z3;

        float4 out = {z0, z1, z2, z3};
        ((float4*)zout)[(size_t)i * 32 + lane] = out;
        gi = batch[i];
    }

    if (lane == 0) sgi[wid] = gi;
    sred[wid][lane * 4 + 0] = z0;
    sred[wid][lane * 4 + 1] = z1;
    sred[wid][lane * 4 + 2] = z2;
    sred[wid][lane * 4 + 3] = z3;
    __syncthreads();

    int g0 = sgi[0];
    bool uni = (g0 >= 0);
    #pragma unroll
    for (int w = 1; w < 8; w++) uni = uni && (sgi[w] == g0);

    if (uni) {
        int f = threadIdx.x;
        if (f < 128) {
            float s = 0.f;
            #pragma unroll
            for (int w = 0; w < 8; w++) s += sred[w][f];
            atomicAdd(&pool[(size_t)g0 * 256 + f], s);
        }
    } else if (valid) {
        float* p = &pool[(size_t)gi * 256 + lane * 4];
        atomicAdd(p + 0, z0);
        atomicAdd(p + 1, z1);
        atomicAdd(p + 2, z2);
        atomicAdd(p + 3, z3);
    }
}

// ---------------- launch -------------------------------------------------------
extern "C" void kernel_launch(void* const* d_in, const int* in_sizes, int n_in,
                              void* d_out, int out_size) {
    const float* x      = (const float*)d_in[0];
    const int*   eidx   = (const int*)d_in[1];
    const int*   batch  = (const int*)d_in[2];
    const float* W0     = (const float*)d_in[3];
    const float* b0     = (const float*)d_in[4];
    const float* alpha0 = (const float*)d_in[5];
    const float* W1     = (const float*)d_in[6];
    const float* b1     = (const float*)d_in[7];
    const float* alpha1 = (const float*)d_in[8];

    int n = in_sizes[0] / HH;       // 50000
    int e = in_sizes[1] / 2;        // 800000
    const int* src = eidx;
    const int* dst = eidx + e;

    float* z2_out = (float*)d_out;                   // [n,128]
    float* g_pool = (float*)d_out + (size_t)n * HH;  // [G, 256]
    int gsize = out_size - n * HH;                   // 65536

    __half* zwh; cudaGetSymbolAddress((void**)&zwh, g_zwh);
    float*  z1;  cudaGetSymbolAddress((void**)&z1, g_z1);

    int nb = (n + SCHUNK - 1) / SCHUNK;
    int count_blocks = (e + 255) / 256;
    int zero_blocks  = (gsize + 255) / 256;
    int gemm_blocks  = (n + 127) / 128;
    int gather_blocks = (n + 7) / 8;

    // Phase A: count degrees + zero pool + GEMM layer 0 (all independent)
    fusedA_kernel<<<count_blocks + zero_blocks + gemm_blocks, 256>>>(
        dst, e, g_pool, gsize, x, W0, zwh, n, count_blocks, zero_blocks);

    // CSR build
    reduce_kernel<<<nb, 256>>>(n);
    scan_write_kernel<<<nb, 256>>>(n);
    fill_kernel<<<count_blocks, 256>>>(src, dst, e);

    // Layer 0 aggregate
    gather_kernel<<<gather_blocks, 256>>>(zwh, b0, alpha0, batch, z1, g_pool, n);
    // Layer 1
    gemm_tf32_kernel<<<gemm_blocks, 256>>>(z1, W1, zwh, n);
    gather_kernel<<<gather_blocks, 256>>>(zwh, b1, alpha1, batch, z2_out,
                                          g_pool + HH, n);
}

// round 6
// speedup vs baseline: 1.9325x; 1.4070x over previous
#include <cuda_runtime.h>
#include <cuda_fp16.h>
#include <cstdint>

#define NN 50000
#define EE 800000
#define HH 128
#define GG 256
#define SCHUNK 512
#define MAXNB 128   // >= ceil(NN/SCHUNK)=98

// ---------------- scratch (device globals: no allocation allowed) -----------
__device__ __half g_zwh[NN * HH];   // z @ W result (fp16)
__device__ __half g_z1h[NN * HH];   // layer-1 activation (fp16)
__device__ __half g_W0h[HH * HH];   // W0 transposed [n][k] fp16
__device__ __half g_W1h[HH * HH];   // W1 transposed [n][k] fp16
__device__ float g_dinv[NN];        // 1/sqrt(deg)
__device__ int   g_cnt[NN];         // degree histogram (INVARIANT: 0 at launch entry)
__device__ int   g_cur[NN];         // fill cursor
__device__ int   g_rowptr[NN + 1];  // CSR row pointers (by dst)
__device__ int   g_col[EE];         // CSR column (src) indices
__device__ int   g_bsum[MAXNB];     // per-chunk sums
__device__ int   g_scan_ctr;        // barrier counter (INVARIANT: 0 at launch entry)

// ---------------- fp16 MMA helper ----------------------------------------------
__device__ __forceinline__ void mma_f16(float c[4],
                                        uint32_t a0, uint32_t a1,
                                        uint32_t a2, uint32_t a3,
                                        uint32_t b0, uint32_t b1) {
    asm volatile(
        "mma.sync.aligned.m16n8k16.row.col.f32.f16.f16.f32 "
        "{%0,%1,%2,%3}, {%4,%5,%6,%7}, {%8,%9}, {%0,%1,%2,%3};"
        : "+f"(c[0]), "+f"(c[1]), "+f"(c[2]), "+f"(c[3])
        : "r"(a0), "r"(a1), "r"(a2), "r"(a3), "r"(b0), "r"(b1));
}

// ---------------- prep: transpose + convert W0/W1 to fp16 [n][k] ---------------
__global__ void __launch_bounds__(256) prep_kernel(
    const float* __restrict__ W0, const float* __restrict__ W1) {
    int idx = blockIdx.x * 256 + threadIdx.x;   // 0..16383
    int k = idx >> 7, nn = idx & 127;
    g_W0h[nn * 128 + k] = __float2half(W0[k * 128 + nn]);
    g_W1h[nn * 128 + k] = __float2half(W1[k * 128 + nn]);
}

// ---------------- fp16 GEMM body: C[128,128 tile] = A[.,128] * W ----------------
// 256 threads, 8 warps, warp tile 32x64, mma m16n8k16, fp32 accum, fp16 out.
// As/Bs layout: [128][40] halves (80B rows, conflict-free b32 frag loads).
// Bs holds W transposed: Bs[n][k].
template <bool AHALF>
__device__ __forceinline__ void gemm_body_h(
    __half (*As)[40], __half (*Bs)[40],
    const float* __restrict__ Af, const __half* __restrict__ Ah,
    const __half* __restrict__ Wh,
    __half* __restrict__ C, int n, int m0) {
    int tid = threadIdx.x;
    int lane = tid & 31, wid = tid >> 5;
    int wm = wid >> 1;              // 0..3 : rows 32*wm
    int wn = wid & 1;               // 0..1 : cols 64*wn

    float acc[2][8][4];
    #pragma unroll
    for (int ms = 0; ms < 2; ms++)
        #pragma unroll
        for (int nt = 0; nt < 8; nt++)
            #pragma unroll
            for (int j = 0; j < 4; j++) acc[ms][nt][j] = 0.0f;

    int rq = lane >> 2;             // 0..7
    int kq = (lane & 3) * 2;        // 0,2,4,6

    for (int k0 = 0; k0 < 128; k0 += 32) {
        // ---- stage A tile [128 rows x 32 k] as halves ----
        #pragma unroll
        for (int it = 0; it < 2; it++) {
            int f = tid + 256 * it;         // 0..511
            int row = f >> 2;
            int k8 = (f & 3) * 8;
            int rg = m0 + row;
            if (rg >= n) rg = n - 1;
            if (AHALF) {
                uint4 v = *(const uint4*)&Ah[(size_t)rg * 128 + k0 + k8];
                *(uint4*)&As[row][k8] = v;
            } else {
                float4 a0 = *(const float4*)&Af[(size_t)rg * 128 + k0 + k8];
                float4 a1 = *(const float4*)&Af[(size_t)rg * 128 + k0 + k8 + 4];
                __half2 h[4];
                h[0] = __floats2half2_rn(a0.x, a0.y);
                h[1] = __floats2half2_rn(a0.z, a0.w);
                h[2] = __floats2half2_rn(a1.x, a1.y);
                h[3] = __floats2half2_rn(a1.z, a1.w);
                *(uint4*)&As[row][k8] = *(uint4*)h;
            }
        }
        // ---- stage B tile: Bs[n][k0..k0+31] from Wh[n][k] ----
        #pragma unroll
        for (int it = 0; it < 2; it++) {
            int f = tid + 256 * it;
            int nr = f >> 2;
            int k8 = (f & 3) * 8;
            uint4 v = *(const uint4*)&Wh[(size_t)nr * 128 + k0 + k8];
            *(uint4*)&Bs[nr][k8] = v;
        }
        __syncthreads();

        #pragma unroll
        for (int kk = 0; kk < 32; kk += 16) {
            // A fragments for both ms subtiles
            uint32_t a[2][4];
            #pragma unroll
            for (int ms = 0; ms < 2; ms++) {
                int r = wm * 32 + ms * 16 + rq;
                a[ms][0] = *(const uint32_t*)&As[r][kk + kq];
                a[ms][1] = *(const uint32_t*)&As[r + 8][kk + kq];
                a[ms][2] = *(const uint32_t*)&As[r][kk + kq + 8];
                a[ms][3] = *(const uint32_t*)&As[r + 8][kk + kq + 8];
            }
            #pragma unroll
            for (int nt = 0; nt < 8; nt++) {
                int nc = wn * 64 + nt * 8 + rq;
                uint32_t b0 = *(const uint32_t*)&Bs[nc][kk + kq];
                uint32_t b1 = *(const uint32_t*)&Bs[nc][kk + kq + 8];
                #pragma unroll
                for (int ms = 0; ms < 2; ms++)
                    mma_f16(acc[ms][nt], a[ms][0], a[ms][1], a[ms][2], a[ms][3], b0, b1);
            }
        }
        __syncthreads();
    }

    // epilogue: fp16 out
    __half2* Ch = (__half2*)C;
    #pragma unroll
    for (int ms = 0; ms < 2; ms++) {
        int r0 = m0 + wm * 32 + ms * 16 + rq;
        #pragma unroll
        for (int nt = 0; nt < 8; nt++) {
            int nc = wn * 64 + nt * 8 + (lane & 3) * 2;
            if (r0 < n)
                Ch[(size_t)r0 * 64 + (nc >> 1)] =
                    __floats2half2_rn(acc[ms][nt][0], acc[ms][nt][1]);
            if (r0 + 8 < n)
                Ch[(size_t)(r0 + 8) * 64 + (nc >> 1)] =
                    __floats2half2_rn(acc[ms][nt][2], acc[ms][nt][3]);
        }
    }
}

// ---------------- fused: GEMM0 | count | pool-zero ------------------------------
__global__ void __launch_bounds__(256) fusedA_kernel(
    const int* __restrict__ dst, int e,
    float* __restrict__ pool, int gsize,
    const float* __restrict__ A, const __half* __restrict__ Wh,
    __half* __restrict__ C, int n, int GB, int CB) {
    __shared__ __half As[128][40];
    __shared__ __half Bs[128][40];
    int b = blockIdx.x;
    int tid = threadIdx.x;
    if (b < GB) {
        gemm_body_h<false>(As, Bs, A, nullptr, Wh, C, n, b * 128);
        return;
    }
    b -= GB;
    if (b < CB) {
        // degree count: 4 edges per thread, independent atomic chains
        int base = b * 1024 + tid;
        int dd[4]; bool v[4];
        #pragma unroll
        for (int j = 0; j < 4; j++) {
            int i = base + j * 256;
            v[j] = i < e;
            dd[j] = v[j] ? dst[i] : 0;
        }
        #pragma unroll
        for (int j = 0; j < 4; j++)
            if (v[j]) atomicAdd(&g_cnt[dd[j]], 1);
        return;
    }
    b -= CB;
    int i = b * 256 + tid;
    if (i < gsize) pool[i] = 0.0f;
}

// ---------------- GEMM layer 1 (A fp16) -----------------------------------------
__global__ void __launch_bounds__(256) gemm1_kernel(
    const __half* __restrict__ Ah, const __half* __restrict__ Wh,
    __half* __restrict__ C, int n) {
    __shared__ __half As[128][40];
    __shared__ __half Bs[128][40];
    gemm_body_h<true>(As, Bs, nullptr, Ah, Wh, C, n, blockIdx.x * 128);
}

// ---------------- merged reduce + scan + write (single wave, 98 blocks) ---------
__global__ void __launch_bounds__(256) scan_all_kernel(int n, int nb) {
    __shared__ int ws[8];
    __shared__ int sadd;
    int b = blockIdx.x, tid = threadIdx.x;
    int lane = tid & 31, wid = tid >> 5;

    // phase 1: chunk sum
    int base = b * SCHUNK + tid * 2;
    int v0 = base < n ? g_cnt[base] : 0;
    int v1 = base + 1 < n ? g_cnt[base + 1] : 0;
    int t = v0 + v1;
    int s = t;
    #pragma unroll
    for (int d = 16; d > 0; d >>= 1) s += __shfl_down_sync(0xFFFFFFFFu, s, d);
    if (lane == 0) ws[wid] = s;
    __syncthreads();
    if (tid == 0) {
        int tot = 0;
        #pragma unroll
        for (int w = 0; w < 8; w++) tot += ws[w];
        g_bsum[b] = tot;
        __threadfence();
        atomicAdd(&g_scan_ctr, 1);
        while (*(volatile int*)&g_scan_ctr < nb) __nanosleep(64);
    }
    __syncthreads();
    __threadfence();

    // phase 2: chunk offset = sum g_bsum[0..b)
    if (tid == 0) sadd = 0;
    __syncthreads();
    int part = 0;
    for (int j = tid; j < b; j += 256) part += g_bsum[j];
    #pragma unroll
    for (int d = 16; d > 0; d >>= 1) part += __shfl_down_sync(0xFFFFFFFFu, part, d);
    if (lane == 0 && part != 0) atomicAdd(&sadd, part);

    // phase 3: local scan + writes
    int x = t;
    #pragma unroll
    for (int d = 1; d < 32; d <<= 1) {
        int y = __shfl_up_sync(0xFFFFFFFFu, x, d);
        if (lane >= d) x += y;
    }
    if (lane == 31) ws[wid] = x;
    __syncthreads();
    int add = sadd;
    for (int w = 0; w < wid; w++) add += ws[w];
    int excl = x - t + add;
    if (base < n) {
        g_rowptr[base + 1] = excl + v0;
        g_cur[base] = excl;
        g_dinv[base] = rsqrtf((float)(v0 + 1));  // +1 self loop
        g_cnt[base] = 0;                         // restore invariant
    }
    if (base + 1 < n) {
        g_rowptr[base + 2] = excl + v0 + v1;
        g_cur[base + 1] = excl + v0;
        g_dinv[base + 1] = rsqrtf((float)(v1 + 1));
        g_cnt[base + 1] = 0;
    }
    if (b == 0 && tid == 0) g_rowptr[0] = 0;
}

// ---------------- CSR fill: 4 edges per thread ----------------------------------
__global__ void __launch_bounds__(256) fill_kernel(
    const int* __restrict__ src, const int* __restrict__ dst, int e) {
    int base = blockIdx.x * 1024 + threadIdx.x;
    int dd[4]; bool v[4]; int pos[4];
    #pragma unroll
    for (int j = 0; j < 4; j++) {
        int i = base + j * 256;
        v[j] = i < e;
        dd[j] = v[j] ? dst[i] : 0;
    }
    #pragma unroll
    for (int j = 0; j < 4; j++)
        if (v[j]) pos[j] = atomicAdd(&g_cur[dd[j]], 1);
    #pragma unroll
    for (int j = 0; j < 4; j++)
        if (v[j]) g_col[pos[j]] = src[base + j * 256];
}

// ---------------- gather (fp16 in) + bias + PReLU + pooled reduction ------------
// OUTHALF: layer-0 writes z1 as fp16; layer-1 writes z2 as fp32 (kernel output).
template <bool OUTHALF>
__global__ void __launch_bounds__(256) gather_kernel(
    const __half* __restrict__ zwh,
    const float* __restrict__ bias,
    const float* __restrict__ alpha,
    const int* __restrict__ batch,
    void* __restrict__ zout,
    float* __restrict__ pool,
    int n, int reset) {
    __shared__ float sred[8][132];
    __shared__ int sgi[8];
    if (reset && blockIdx.x == 0 && threadIdx.x == 0) g_scan_ctr = 0;
    int wid = threadIdx.x >> 5, lane = threadIdx.x & 31;
    int i = blockIdx.x * 8 + wid;
    bool valid = i < n;

    float z0 = 0.f, z1 = 0.f, z2 = 0.f, z3 = 0.f;
    int gi = -1;

    if (valid) {
        const uint2* __restrict__ zwv = (const uint2*)zwh;  // 4 halves per lane
        float di = g_dinv[i];

        uint2 sv = zwv[(size_t)i * 32 + lane];
        float2 f0 = __half22float2(*(const __half2*)&sv.x);
        float2 f1 = __half22float2(*(const __half2*)&sv.y);
        float4 acc;
        acc.x = di * f0.x; acc.y = di * f0.y;
        acc.z = di * f1.x; acc.w = di * f1.y;

        int e0 = g_rowptr[i], e1 = g_rowptr[i + 1];
        int e = e0;
        for (; e + 4 <= e1; e += 4) {
            int s0 = g_col[e + 0];
            int s1 = g_col[e + 1];
            int s2 = g_col[e + 2];
            int s3 = g_col[e + 3];
            uint2 u0 = zwv[(size_t)s0 * 32 + lane];
            uint2 u1 = zwv[(size_t)s1 * 32 + lane];
            uint2 u2 = zwv[(size_t)s2 * 32 + lane];
            uint2 u3 = zwv[(size_t)s3 * 32 + lane];
            float d0 = g_dinv[s0], d1 = g_dinv[s1];
            float d2 = g_dinv[s2], d3 = g_dinv[s3];
            float2 a0 = __half22float2(*(const __half2*)&u0.x);
            float2 b0 = __half22float2(*(const __half2*)&u0.y);
            float2 a1 = __half22float2(*(const __half2*)&u1.x);
            float2 b1 = __half22float2(*(const __half2*)&u1.y);
            float2 a2 = __half22float2(*(const __half2*)&u2.x);
            float2 b2 = __half22float2(*(const __half2*)&u2.y);
            float2 a3 = __half22float2(*(const __half2*)&u3.x);
            float2 b3 = __half22float2(*(const __half2*)&u3.y);
            acc.x = fmaf(d0, a0.x, fmaf(d1, a1.x, fmaf(d2, a2.x, fmaf(d3, a3.x, acc.x))));
            acc.y = fmaf(d0, a0.y, fmaf(d1, a1.y, fmaf(d2, a2.y, fmaf(d3, a3.y, acc.y))));
            acc.z = fmaf(d0, b0.x, fmaf(d1, b1.x, fmaf(d2, b2.x, fmaf(d3, b3.x, acc.z))));
            acc.w = fmaf(d0, b0.y, fmaf(d1, b1.y, fmaf(d2, b2.y, fmaf(d3, b3.y, acc.w))));
        }
        for (; e < e1; e++) {
            int s = g_col[e];
            float ds = g_dinv[s];
            uint2 u = zwv[(size_t)s * 32 + lane];
            float2 a = __half22float2(*(const __half2*)&u.x);
            float2 c = __half22float2(*(const __half2*)&u.y);
            acc.x = fmaf(ds, a.x, acc.x);
            acc.y = fmaf(ds, a.y, acc.y);
            acc.z = fmaf(ds, c.x, acc.z);
            acc.w = fmaf(ds, c.y, acc.w);
        }

        float4 b  = ((const float4*)bias)[lane];
        float4 al = ((const float4*)alpha)[lane];
        z0 = fmaf(acc.x, di, b.x);
        z1 = fmaf(acc.y, di, b.y);
        z2 = fmaf(acc.z, di, b.z);
        z3 = fmaf(acc.w, di, b.w);
        z0 = z0 > 0.0f ? z0 : al.x * z0;
        z1 = z1 > 0.0f ? z1 : al.y * z1;
        z2 = z2 > 0.0f ? z2 : al.z * z2;
        z3 = z3 > 0.0f ? z3 : al.w * z3;

        if (OUTHALF) {
            __half2 h[2];
            h[0] = __floats2half2_rn(z0, z1);
            h[1] = __floats2half2_rn(z2, z3);
            ((uint2*)zout)[(size_t)i * 32 + lane] = *(uint2*)h;
        } else {
            float4 out = {z0, z1, z2, z3};
            ((float4*)zout)[(size_t)i * 32 + lane] = out;
        }
        gi = batch[i];
    }

    if (lane == 0) sgi[wid] = gi;
    sred[wid][lane * 4 + 0] = z0;
    sred[wid][lane * 4 + 1] = z1;
    sred[wid][lane * 4 + 2] = z2;
    sred[wid][lane * 4 + 3] = z3;
    __syncthreads();

    int g0 = sgi[0];
    bool uni = (g0 >= 0);
    #pragma unroll
    for (int w = 1; w < 8; w++) uni = uni && (sgi[w] == g0);

    if (uni) {
        int f = threadIdx.x;
        if (f < 128) {
            float s = 0.f;
            #pragma unroll
            for (int w = 0; w < 8; w++) s += sred[w][f];
            atomicAdd(&pool[(size_t)g0 * 256 + f], s);
        }
    } else if (valid) {
        float* p = &pool[(size_t)gi * 256 + lane * 4];
        atomicAdd(p + 0, z0);
        atomicAdd(p + 1, z1);
        atomicAdd(p + 2, z2);
        atomicAdd(p + 3, z3);
    }
}

// ---------------- launch ----------------------------------------------------------
extern "C" void kernel_launch(void* const* d_in, const int* in_sizes, int n_in,
                              void* d_out, int out_size) {
    const float* x      = (const float*)d_in[0];
    const int*   eidx   = (const int*)d_in[1];
    const int*   batch  = (const int*)d_in[2];
    const float* W0     = (const float*)d_in[3];
    const float* b0     = (const float*)d_in[4];
    const float* alpha0 = (const float*)d_in[5];
    const float* W1     = (const float*)d_in[6];
    const float* b1     = (const float*)d_in[7];
    const float* alpha1 = (const float*)d_in[8];

    int n = in_sizes[0] / HH;       // 50000
    int e = in_sizes[1] / 2;        // 800000
    const int* src = eidx;
    const int* dst = eidx + e;

    float* z2_out = (float*)d_out;                   // [n,128]
    float* g_pool = (float*)d_out + (size_t)n * HH;  // [G, 256]
    int gsize = out_size - n * HH;                   // 65536

    __half* zwh;  cudaGetSymbolAddress((void**)&zwh, g_zwh);
    __half* z1h;  cudaGetSymbolAddress((void**)&z1h, g_z1h);
    __half* W0h;  cudaGetSymbolAddress((void**)&W0h, g_W0h);
    __half* W1h;  cudaGetSymbolAddress((void**)&W1h, g_W1h);

    int nb = (n + SCHUNK - 1) / SCHUNK;          // 98
    int GB = (n + 127) / 128;                    // 391
    int CB = (e + 1023) / 1024;                  // 782 (4 edges/thread)
    int ZB = (gsize + 255) / 256;                // 256
    int FB = CB;
    int gather_blocks = (n + 7) / 8;

    // W transpose+convert (needed by GEMM0)
    prep_kernel<<<64, 256>>>(W0, W1);

    // Phase A: GEMM0 first (starts immediately), count + pool-zero behind
    fusedA_kernel<<<GB + CB + ZB, 256>>>(
        dst, e, g_pool, gsize, x, W0h, zwh, n, GB, CB);

    // CSR build
    scan_all_kernel<<<nb, 256>>>(n, nb);
    fill_kernel<<<FB, 256>>>(src, dst, e);

    // Layer 0 aggregate (also resets scan counter); writes z1 as fp16
    gather_kernel<true><<<gather_blocks, 256>>>(
        zwh, b0, alpha0, batch, z1h, g_pool, n, 1);
    // Layer 1
    gemm1_kernel<<<GB, 256>>>(z1h, W1h, zwh, n);
    gather_kernel<false><<<gather_blocks, 256>>>(
        zwh, b1, alpha1, batch, z2_out, g_pool + HH, n, 0);
}

// round 7
// speedup vs baseline: 1.9992x; 1.0345x over previous
#include <cuda_runtime.h>
#include <cuda_fp16.h>
#include <cstdint>

#define NN 50000
#define EE 800000
#define HH 128
#define GG 256
#define SCHUNK 512
#define MAXNB 128   // >= ceil(NN/SCHUNK)=98

// ---------------- scratch (device globals: no allocation allowed) -----------
__device__ __half g_zwh[NN * HH];   // dinv-scaled z @ W (fp16)
__device__ __half g_z1h[NN * HH];   // layer-1 activation (fp16)
__device__ __half g_W0h[HH * HH];   // W0 transposed [n][k] fp16
__device__ __half g_W1h[HH * HH];   // W1 transposed [n][k] fp16
__device__ float g_dinv[NN];        // 1/sqrt(deg)
__device__ int   g_cnt[NN];         // degree histogram (INVARIANT: 0 at launch entry)
__device__ int   g_cur[NN];         // fill cursor
__device__ int   g_rowptr[NN + 1];  // CSR row pointers (by dst)
__device__ int   g_col[EE];         // CSR column (src) indices
__device__ int   g_bsum[MAXNB];     // per-chunk sums
__device__ int   g_scan_ctr;        // barrier counter (INVARIANT: 0 at launch entry)

// ---------------- fp16 MMA helper ----------------------------------------------
__device__ __forceinline__ void mma_f16(float c[4],
                                        uint32_t a0, uint32_t a1,
                                        uint32_t a2, uint32_t a3,
                                        uint32_t b0, uint32_t b1) {
    asm volatile(
        "mma.sync.aligned.m16n8k16.row.col.f32.f16.f16.f32 "
        "{%0,%1,%2,%3}, {%4,%5,%6,%7}, {%8,%9}, {%0,%1,%2,%3};"
        : "+f"(c[0]), "+f"(c[1]), "+f"(c[2]), "+f"(c[3])
        : "r"(a0), "r"(a1), "r"(a2), "r"(a3), "r"(b0), "r"(b1));
}

// ---------------- fp16 GEMM body: C[r] = dinv[r] * (A[r,:] @ W)  ----------------
// 256 threads, 8 warps, warp tile 32x64, mma m16n8k16, fp32 accum,
// dinv-scaled fp16 out.
template <bool AHALF>
__device__ __forceinline__ void gemm_body_h(
    __half (*As)[40], __half (*Bs)[40],
    const float* __restrict__ Af, const __half* __restrict__ Ah,
    const __half* __restrict__ Wh,
    __half* __restrict__ C, int n, int m0) {
    int tid = threadIdx.x;
    int lane = tid & 31, wid = tid >> 5;
    int wm = wid >> 1;              // 0..3 : rows 32*wm
    int wn = wid & 1;               // 0..1 : cols 64*wn

    float acc[2][8][4];
    #pragma unroll
    for (int ms = 0; ms < 2; ms++)
        #pragma unroll
        for (int nt = 0; nt < 8; nt++)
            #pragma unroll
            for (int j = 0; j < 4; j++) acc[ms][nt][j] = 0.0f;

    int rq = lane >> 2;             // 0..7
    int kq = (lane & 3) * 2;        // 0,2,4,6

    for (int k0 = 0; k0 < 128; k0 += 32) {
        #pragma unroll
        for (int it = 0; it < 2; it++) {
            int f = tid + 256 * it;
            int row = f >> 2;
            int k8 = (f & 3) * 8;
            int rg = m0 + row;
            if (rg >= n) rg = n - 1;
            if (AHALF) {
                uint4 v = *(const uint4*)&Ah[(size_t)rg * 128 + k0 + k8];
                *(uint4*)&As[row][k8] = v;
            } else {
                float4 a0 = *(const float4*)&Af[(size_t)rg * 128 + k0 + k8];
                float4 a1 = *(const float4*)&Af[(size_t)rg * 128 + k0 + k8 + 4];
                __half2 h[4];
                h[0] = __floats2half2_rn(a0.x, a0.y);
                h[1] = __floats2half2_rn(a0.z, a0.w);
                h[2] = __floats2half2_rn(a1.x, a1.y);
                h[3] = __floats2half2_rn(a1.z, a1.w);
                *(uint4*)&As[row][k8] = *(uint4*)h;
            }
        }
        #pragma unroll
        for (int it = 0; it < 2; it++) {
            int f = tid + 256 * it;
            int nr = f >> 2;
            int k8 = (f & 3) * 8;
            uint4 v = *(const uint4*)&Wh[(size_t)nr * 128 + k0 + k8];
            *(uint4*)&Bs[nr][k8] = v;
        }
        __syncthreads();

        #pragma unroll
        for (int kk = 0; kk < 32; kk += 16) {
            uint32_t a[2][4];
            #pragma unroll
            for (int ms = 0; ms < 2; ms++) {
                int r = wm * 32 + ms * 16 + rq;
                a[ms][0] = *(const uint32_t*)&As[r][kk + kq];
                a[ms][1] = *(const uint32_t*)&As[r + 8][kk + kq];
                a[ms][2] = *(const uint32_t*)&As[r][kk + kq + 8];
                a[ms][3] = *(const uint32_t*)&As[r + 8][kk + kq + 8];
            }
            #pragma unroll
            for (int nt = 0; nt < 8; nt++) {
                int nc = wn * 64 + nt * 8 + rq;
                uint32_t b0 = *(const uint32_t*)&Bs[nc][kk + kq];
                uint32_t b1 = *(const uint32_t*)&Bs[nc][kk + kq + 8];
                #pragma unroll
                for (int ms = 0; ms < 2; ms++)
                    mma_f16(acc[ms][nt], a[ms][0], a[ms][1], a[ms][2], a[ms][3], b0, b1);
            }
        }
        __syncthreads();
    }

    // epilogue: scale by dinv[row], convert to fp16
    __half2* Ch = (__half2*)C;
    #pragma unroll
    for (int ms = 0; ms < 2; ms++) {
        int r0 = m0 + wm * 32 + ms * 16 + rq;
        float di0 = (r0 < n) ? g_dinv[r0] : 0.0f;
        float di8 = (r0 + 8 < n) ? g_dinv[r0 + 8] : 0.0f;
        #pragma unroll
        for (int nt = 0; nt < 8; nt++) {
            int nc = wn * 64 + nt * 8 + (lane & 3) * 2;
            if (r0 < n)
                Ch[(size_t)r0 * 64 + (nc >> 1)] =
                    __floats2half2_rn(di0 * acc[ms][nt][0], di0 * acc[ms][nt][1]);
            if (r0 + 8 < n)
                Ch[(size_t)(r0 + 8) * 64 + (nc >> 1)] =
                    __floats2half2_rn(di8 * acc[ms][nt][2], di8 * acc[ms][nt][3]);
        }
    }
}

// ---------------- fusedA: count | W-prep | pool-zero -----------------------------
__global__ void __launch_bounds__(256) fusedA_kernel(
    const int* __restrict__ dst, int e,
    float* __restrict__ pool, int gsize,
    const float* __restrict__ W0, const float* __restrict__ W1,
    int CB, int PB) {
    int b = blockIdx.x;
    int tid = threadIdx.x;
    if (b < CB) {
        int i = b * 256 + tid;
        if (i < e) atomicAdd(&g_cnt[dst[i]], 1);
        return;
    }
    b -= CB;
    if (b < PB) {
        int idx = b * 256 + tid;   // 0..16383
        int k = idx >> 7, nn = idx & 127;
        g_W0h[nn * 128 + k] = __float2half(W0[k * 128 + nn]);
        g_W1h[nn * 128 + k] = __float2half(W1[k * 128 + nn]);
        return;
    }
    b -= PB;
    int i = b * 256 + tid;
    if (i < gsize) pool[i] = 0.0f;
}

// ---------------- merged reduce + scan + write (single wave, 98 blocks) ---------
__global__ void __launch_bounds__(256) scan_all_kernel(int n, int nb) {
    __shared__ int ws[8];
    __shared__ int sadd;
    int b = blockIdx.x, tid = threadIdx.x;
    int lane = tid & 31, wid = tid >> 5;

    int base = b * SCHUNK + tid * 2;
    int v0 = base < n ? g_cnt[base] : 0;
    int v1 = base + 1 < n ? g_cnt[base + 1] : 0;
    int t = v0 + v1;
    int s = t;
    #pragma unroll
    for (int d = 16; d > 0; d >>= 1) s += __shfl_down_sync(0xFFFFFFFFu, s, d);
    if (lane == 0) ws[wid] = s;
    __syncthreads();
    if (tid == 0) {
        int tot = 0;
        #pragma unroll
        for (int w = 0; w < 8; w++) tot += ws[w];
        g_bsum[b] = tot;
        __threadfence();
        atomicAdd(&g_scan_ctr, 1);
        while (*(volatile int*)&g_scan_ctr < nb) __nanosleep(64);
    }
    __syncthreads();
    __threadfence();

    if (tid == 0) sadd = 0;
    __syncthreads();
    int part = 0;
    for (int j = tid; j < b; j += 256) part += g_bsum[j];
    #pragma unroll
    for (int d = 16; d > 0; d >>= 1) part += __shfl_down_sync(0xFFFFFFFFu, part, d);
    if (lane == 0 && part != 0) atomicAdd(&sadd, part);

    int x = t;
    #pragma unroll
    for (int d = 1; d < 32; d <<= 1) {
        int y = __shfl_up_sync(0xFFFFFFFFu, x, d);
        if (lane >= d) x += y;
    }
    if (lane == 31) ws[wid] = x;
    __syncthreads();
    int add = sadd;
    for (int w = 0; w < wid; w++) add += ws[w];
    int excl = x - t + add;
    if (base < n) {
        g_rowptr[base + 1] = excl + v0;
        g_cur[base] = excl;
        g_dinv[base] = rsqrtf((float)(v0 + 1));  // +1 self loop
        g_cnt[base] = 0;                         // restore invariant
    }
    if (base + 1 < n) {
        g_rowptr[base + 2] = excl + v0 + v1;
        g_cur[base + 1] = excl + v0;
        g_dinv[base + 1] = rsqrtf((float)(v1 + 1));
        g_cnt[base + 1] = 0;
    }
    if (b == 0 && tid == 0) g_rowptr[0] = 0;
}

// ---------------- fusedB: CSR fill (critical path) | GEMM0 (off-path) -----------
__global__ void __launch_bounds__(256) fusedB_kernel(
    const int* __restrict__ src, const int* __restrict__ dst, int e,
    const float* __restrict__ A, const __half* __restrict__ Wh,
    __half* __restrict__ C, int n, int FB) {
    __shared__ __half As[128][40];
    __shared__ __half Bs[128][40];
    int b = blockIdx.x;
    if (b < FB) {
        int i = b * 256 + threadIdx.x;
        if (i < e) {
            int pos = atomicAdd(&g_cur[dst[i]], 1);
            g_col[pos] = src[i];
        }
        return;
    }
    gemm_body_h<false>(As, Bs, A, nullptr, Wh, C, n, (b - FB) * 128);
}

// ---------------- GEMM layer 1 (A fp16) -----------------------------------------
__global__ void __launch_bounds__(256) gemm1_kernel(
    const __half* __restrict__ Ah, const __half* __restrict__ Wh,
    __half* __restrict__ C, int n) {
    __shared__ __half As[128][40];
    __shared__ __half Bs[128][40];
    gemm_body_h<true>(As, Bs, nullptr, Ah, Wh, C, n, blockIdx.x * 128);
}

// ---------------- gather (dinv-scaled fp16 in) + bias + PReLU + pool ------------
// out[i] = prelu(dinv[i] * (zws[i] + sum_src zws[src]) + b)
template <bool OUTHALF>
__global__ void __launch_bounds__(256) gather_kernel(
    const __half* __restrict__ zws,
    const float* __restrict__ bias,
    const float* __restrict__ alpha,
    const int* __restrict__ batch,
    void* __restrict__ zout,
    float* __restrict__ pool,
    int n, int reset) {
    __shared__ float sred[8][132];
    __shared__ int sgi[8];
    if (reset && blockIdx.x == 0 && threadIdx.x == 0) g_scan_ctr = 0;
    int wid = threadIdx.x >> 5, lane = threadIdx.x & 31;
    int i = blockIdx.x * 8 + wid;
    bool valid = i < n;

    float z0 = 0.f, z1 = 0.f, z2 = 0.f, z3 = 0.f;
    int gi = -1;

    if (valid) {
        const uint2* __restrict__ zwv = (const uint2*)zws;  // 4 halves per lane
        float di = g_dinv[i];

        uint2 sv = zwv[(size_t)i * 32 + lane];
        float2 f0 = __half22float2(*(const __half2*)&sv.x);
        float2 f1 = __half22float2(*(const __half2*)&sv.y);
        float4 acc = {f0.x, f0.y, f1.x, f1.y};

        int e0 = g_rowptr[i], e1 = g_rowptr[i + 1];
        int e = e0;
        for (; e + 4 <= e1; e += 4) {
            int s0 = g_col[e + 0];
            int s1 = g_col[e + 1];
            int s2 = g_col[e + 2];
            int s3 = g_col[e + 3];
            uint2 u0 = zwv[(size_t)s0 * 32 + lane];
            uint2 u1 = zwv[(size_t)s1 * 32 + lane];
            uint2 u2 = zwv[(size_t)s2 * 32 + lane];
            uint2 u3 = zwv[(size_t)s3 * 32 + lane];
            float2 a0 = __half22float2(*(const __half2*)&u0.x);
            float2 b0 = __half22float2(*(const __half2*)&u0.y);
            float2 a1 = __half22float2(*(const __half2*)&u1.x);
            float2 b1 = __half22float2(*(const __half2*)&u1.y);
            float2 a2 = __half22float2(*(const __half2*)&u2.x);
            float2 b2 = __half22float2(*(const __half2*)&u2.y);
            float2 a3 = __half22float2(*(const __half2*)&u3.x);
            float2 b3 = __half22float2(*(const __half2*)&u3.y);
            acc.x += (a0.x + a1.x) + (a2.x + a3.x);
            acc.y += (a0.y + a1.y) + (a2.y + a3.y);
            acc.z += (b0.x + b1.x) + (b2.x + b3.x);
            acc.w += (b0.y + b1.y) + (b2.y + b3.y);
        }
        for (; e < e1; e++) {
            int s = g_col[e];
            uint2 u = zwv[(size_t)s * 32 + lane];
            float2 a = __half22float2(*(const __half2*)&u.x);
            float2 c = __half22float2(*(const __half2*)&u.y);
            acc.x += a.x;
            acc.y += a.y;
            acc.z += c.x;
            acc.w += c.y;
        }

        float4 b  = ((const float4*)bias)[lane];
        float4 al = ((const float4*)alpha)[lane];
        z0 = fmaf(acc.x, di, b.x);
        z1 = fmaf(acc.y, di, b.y);
        z2 = fmaf(acc.z, di, b.z);
        z3 = fmaf(acc.w, di, b.w);
        z0 = z0 > 0.0f ? z0 : al.x * z0;
        z1 = z1 > 0.0f ? z1 : al.y * z1;
        z2 = z2 > 0.0f ? z2 : al.z * z2;
        z3 = z3 > 0.0f ? z3 : al.w * z3;

        if (OUTHALF) {
            __half2 h[2];
            h[0] = __floats2half2_rn(z0, z1);
            h[1] = __floats2half2_rn(z2, z3);
            ((uint2*)zout)[(size_t)i * 32 + lane] = *(uint2*)h;
        } else {
            float4 out = {z0, z1, z2, z3};
            ((float4*)zout)[(size_t)i * 32 + lane] = out;
        }
        gi = batch[i];
    }

    if (lane == 0) sgi[wid] = gi;
    sred[wid][lane * 4 + 0] = z0;
    sred[wid][lane * 4 + 1] = z1;
    sred[wid][lane * 4 + 2] = z2;
    sred[wid][lane * 4 + 3] = z3;
    __syncthreads();

    int g0 = sgi[0];
    bool uni = (g0 >= 0);
    #pragma unroll
    for (int w = 1; w < 8; w++) uni = uni && (sgi[w] == g0);

    if (uni) {
        int f = threadIdx.x;
        if (f < 128) {
            float s = 0.f;
            #pragma unroll
            for (int w = 0; w < 8; w++) s += sred[w][f];
            atomicAdd(&pool[(size_t)g0 * 256 + f], s);
        }
    } else if (valid) {
        float* p = &pool[(size_t)gi * 256 + lane * 4];
        atomicAdd(p + 0, z0);
        atomicAdd(p + 1, z1);
        atomicAdd(p + 2, z2);
        atomicAdd(p + 3, z3);
    }
}

// ---------------- launch ----------------------------------------------------------
extern "C" void kernel_launch(void* const* d_in, const int* in_sizes, int n_in,
                              void* d_out, int out_size) {
    const float* x      = (const float*)d_in[0];
    const int*   eidx   = (const int*)d_in[1];
    const int*   batch  = (const int*)d_in[2];
    const float* W0     = (const float*)d_in[3];
    const float* b0     = (const float*)d_in[4];
    const float* alpha0 = (const float*)d_in[5];
    const float* W1     = (const float*)d_in[6];
    const float* b1     = (const float*)d_in[7];
    const float* alpha1 = (const float*)d_in[8];

    int n = in_sizes[0] / HH;       // 50000
    int e = in_sizes[1] / 2;        // 800000
    const int* src = eidx;
    const int* dst = eidx + e;

    float* z2_out = (float*)d_out;                   // [n,128]
    float* g_pool = (float*)d_out + (size_t)n * HH;  // [G, 256]
    int gsize = out_size - n * HH;                   // 65536

    __half* zwh;  cudaGetSymbolAddress((void**)&zwh, g_zwh);
    __half* z1h;  cudaGetSymbolAddress((void**)&z1h, g_z1h);
    __half* W0h;  cudaGetSymbolAddress((void**)&W0h, g_W0h);
    __half* W1h;  cudaGetSymbolAddress((void**)&W1h, g_W1h);

    int nb = (n + SCHUNK - 1) / SCHUNK;          // 98
    int GB = (n + 127) / 128;                    // 391
    int CB = (e + 255) / 256;                    // 3125
    int PB = 64;                                 // W prep blocks
    int ZB = (gsize + 255) / 256;                // 256
    int FB = CB;
    int gather_blocks = (n + 7) / 8;

    // Phase A: degree count + W fp16 transpose + pool zero (all independent)
    fusedA_kernel<<<CB + PB + ZB, 256>>>(dst, e, g_pool, gsize, W0, W1, CB, PB);

    // CSR offsets + dinv
    scan_all_kernel<<<nb, 256>>>(n, nb);

    // Phase B: CSR fill (critical path) + GEMM0 (hidden behind fill)
    fusedB_kernel<<<FB + GB, 256>>>(src, dst, e, x, W0h, zwh, n, FB);

    // Layer 0 aggregate (also resets scan counter); writes z1 as fp16
    gather_kernel<true><<<gather_blocks, 256>>>(
        zwh, b0, alpha0, batch, z1h, g_pool, n, 1);
    // Layer 1
    gemm1_kernel<<<GB, 256>>>(z1h, W1h, zwh, n);
    gather_kernel<false><<<gather_blocks, 256>>>(
        zwh, b1, alpha1, batch, z2_out, g_pool + HH, n, 0);
}

// round 9
// speedup vs baseline: 2.0360x; 1.0184x over previous
#include <cuda_runtime.h>
#include <cuda_fp16.h>
#include <cstdint>

#define NN 50000
#define EE 800000
#define HH 128
#define GG 256
#define SCHUNK 512
#define MAXNB 128   // >= ceil(NN/SCHUNK)=98

// ---------------- scratch (device globals: no allocation allowed) -----------
__device__ __half g_zwh[NN * HH];   // dinv-scaled z @ W (fp16)
__device__ __half g_z1h[NN * HH];   // layer-1 activation (fp16)
__device__ __half g_W0h[HH * HH];   // W0 transposed [n][k] fp16
__device__ __half g_W1h[HH * HH];   // W1 transposed [n][k] fp16
__device__ float g_dinv[NN];        // 1/sqrt(deg)
__device__ int   g_cnt[NN];         // degree histogram (INVARIANT: 0 at launch entry)
__device__ int   g_cur[NN];         // fill cursor
__device__ int   g_rowptr[NN + 1];  // CSR row pointers (by dst)
__device__ int   g_col[EE];         // CSR column (src) indices
__device__ int   g_bsum[MAXNB];     // per-chunk sums
__device__ int   g_scan_ctr;        // barrier counter (INVARIANT: 0 at launch entry)

// ---------------- fp16 MMA helper ----------------------------------------------
__device__ __forceinline__ void mma_f16(float c[4],
                                        uint32_t a0, uint32_t a1,
                                        uint32_t a2, uint32_t a3,
                                        uint32_t b0, uint32_t b1) {
    asm volatile(
        "mma.sync.aligned.m16n8k16.row.col.f32.f16.f16.f32 "
        "{%0,%1,%2,%3}, {%4,%5,%6,%7}, {%8,%9}, {%0,%1,%2,%3};"
        : "+f"(c[0]), "+f"(c[1]), "+f"(c[2]), "+f"(c[3])
        : "r"(a0), "r"(a1), "r"(a2), "r"(a3), "r"(b0), "r"(b1));
}

// ---------------- fp16 GEMM body: C[r] = dinv[r] * (A[r,:] @ W)  ----------------
template <bool AHALF>
__device__ __forceinline__ void gemm_body_h(
    __half (*As)[40], __half (*Bs)[40],
    const float* __restrict__ Af, const __half* __restrict__ Ah,
    const __half* __restrict__ Wh,
    __half* __restrict__ C, int n, int m0) {
    int tid = threadIdx.x;
    int lane = tid & 31, wid = tid >> 5;
    int wm = wid >> 1;
    int wn = wid & 1;

    float acc[2][8][4];
    #pragma unroll
    for (int ms = 0; ms < 2; ms++)
        #pragma unroll
        for (int nt = 0; nt < 8; nt++)
            #pragma unroll
            for (int j = 0; j < 4; j++) acc[ms][nt][j] = 0.0f;

    int rq = lane >> 2;
    int kq = (lane & 3) * 2;

    for (int k0 = 0; k0 < 128; k0 += 32) {
        #pragma unroll
        for (int it = 0; it < 2; it++) {
            int f = tid + 256 * it;
            int row = f >> 2;
            int k8 = (f & 3) * 8;
            int rg = m0 + row;
            if (rg >= n) rg = n - 1;
            if (AHALF) {
                uint4 v = *(const uint4*)&Ah[(size_t)rg * 128 + k0 + k8];
                *(uint4*)&As[row][k8] = v;
            } else {
                float4 a0 = *(const float4*)&Af[(size_t)rg * 128 + k0 + k8];
                float4 a1 = *(const float4*)&Af[(size_t)rg * 128 + k0 + k8 + 4];
                __half2 h[4];
                h[0] = __floats2half2_rn(a0.x, a0.y);
                h[1] = __floats2half2_rn(a0.z, a0.w);
                h[2] = __floats2half2_rn(a1.x, a1.y);
                h[3] = __floats2half2_rn(a1.z, a1.w);
                *(uint4*)&As[row][k8] = *(uint4*)h;
            }
        }
        #pragma unroll
        for (int it = 0; it < 2; it++) {
            int f = tid + 256 * it;
            int nr = f >> 2;
            int k8 = (f & 3) * 8;
            uint4 v = *(const uint4*)&Wh[(size_t)nr * 128 + k0 + k8];
            *(uint4*)&Bs[nr][k8] = v;
        }
        __syncthreads();

        #pragma unroll
        for (int kk = 0; kk < 32; kk += 16) {
            uint32_t a[2][4];
            #pragma unroll
            for (int ms = 0; ms < 2; ms++) {
                int r = wm * 32 + ms * 16 + rq;
                a[ms][0] = *(const uint32_t*)&As[r][kk + kq];
                a[ms][1] = *(const uint32_t*)&As[r + 8][kk + kq];
                a[ms][2] = *(const uint32_t*)&As[r][kk + kq + 8];
                a[ms][3] = *(const uint32_t*)&As[r + 8][kk + kq + 8];
            }
            #pragma unroll
            for (int nt = 0; nt < 8; nt++) {
                int nc = wn * 64 + nt * 8 + rq;
                uint32_t b0 = *(const uint32_t*)&Bs[nc][kk + kq];
                uint32_t b1 = *(const uint32_t*)&Bs[nc][kk + kq + 8];
                #pragma unroll
                for (int ms = 0; ms < 2; ms++)
                    mma_f16(acc[ms][nt], a[ms][0], a[ms][1], a[ms][2], a[ms][3], b0, b1);
            }
        }
        __syncthreads();
    }

    __half2* Ch = (__half2*)C;
    #pragma unroll
    for (int ms = 0; ms < 2; ms++) {
        int r0 = m0 + wm * 32 + ms * 16 + rq;
        float di0 = (r0 < n) ? g_dinv[r0] : 0.0f;
        float di8 = (r0 + 8 < n) ? g_dinv[r0 + 8] : 0.0f;
        #pragma unroll
        for (int nt = 0; nt < 8; nt++) {
            int nc = wn * 64 + nt * 8 + (lane & 3) * 2;
            if (r0 < n)
                Ch[(size_t)r0 * 64 + (nc >> 1)] =
                    __floats2half2_rn(di0 * acc[ms][nt][0], di0 * acc[ms][nt][1]);
            if (r0 + 8 < n)
                Ch[(size_t)(r0 + 8) * 64 + (nc >> 1)] =
                    __floats2half2_rn(di8 * acc[ms][nt][2], di8 * acc[ms][nt][3]);
        }
    }
}

// ---------------- fusedA: count | W-prep | pool-zero -----------------------------
__global__ void __launch_bounds__(256) fusedA_kernel(
    const int* __restrict__ dst, int e,
    float* __restrict__ pool, int gsize,
    const float* __restrict__ W0, const float* __restrict__ W1,
    int CB, int PB) {
    int b = blockIdx.x;
    int tid = threadIdx.x;
    if (b < CB) {
        int i = b * 256 + tid;
        if (i < e) atomicAdd(&g_cnt[dst[i]], 1);
        return;
    }
    b -= CB;
    if (b < PB) {
        int idx = b * 256 + tid;
        int k = idx >> 7, nn = idx & 127;
        g_W0h[nn * 128 + k] = __float2half(W0[k * 128 + nn]);
        g_W1h[nn * 128 + k] = __float2half(W1[k * 128 + nn]);
        return;
    }
    b -= PB;
    int i = b * 256 + tid;
    if (i < gsize) pool[i] = 0.0f;
}

// ---------------- merged reduce + scan + write (single wave, 98 blocks) ---------
__global__ void __launch_bounds__(256) scan_all_kernel(int n, int nb) {
    __shared__ int ws[8];
    __shared__ int sadd;
    int b = blockIdx.x, tid = threadIdx.x;
    int lane = tid & 31, wid = tid >> 5;

    int base = b * SCHUNK + tid * 2;
    int v0 = base < n ? g_cnt[base] : 0;
    int v1 = base + 1 < n ? g_cnt[base + 1] : 0;
    int t = v0 + v1;
    int s = t;
    #pragma unroll
    for (int d = 16; d > 0; d >>= 1) s += __shfl_down_sync(0xFFFFFFFFu, s, d);
    if (lane == 0) ws[wid] = s;
    __syncthreads();
    if (tid == 0) {
        int tot = 0;
        #pragma unroll
        for (int w = 0; w < 8; w++) tot += ws[w];
        g_bsum[b] = tot;
        __threadfence();
        atomicAdd(&g_scan_ctr, 1);
        while (*(volatile int*)&g_scan_ctr < nb) __nanosleep(64);
    }
    __syncthreads();
    __threadfence();

    if (tid == 0) sadd = 0;
    __syncthreads();
    int part = 0;
    for (int j = tid; j < b; j += 256) part += g_bsum[j];
    #pragma unroll
    for (int d = 16; d > 0; d >>= 1) part += __shfl_down_sync(0xFFFFFFFFu, part, d);
    if (lane == 0 && part != 0) atomicAdd(&sadd, part);

    int x = t;
    #pragma unroll
    for (int d = 1; d < 32; d <<= 1) {
        int y = __shfl_up_sync(0xFFFFFFFFu, x, d);
        if (lane >= d) x += y;
    }
    if (lane == 31) ws[wid] = x;
    __syncthreads();
    int add = sadd;
    for (int w = 0; w < wid; w++) add += ws[w];
    int excl = x - t + add;
    if (base < n) {
        g_rowptr[base + 1] = excl + v0;
        g_cur[base] = excl;
        g_dinv[base] = rsqrtf((float)(v0 + 1));  // +1 self loop
        g_cnt[base] = 0;                         // restore invariant
    }
    if (base + 1 < n) {
        g_rowptr[base + 2] = excl + v0 + v1;
        g_cur[base + 1] = excl + v0;
        g_dinv[base + 1] = rsqrtf((float)(v1 + 1));
        g_cnt[base + 1] = 0;
    }
    if (b == 0 && tid == 0) g_rowptr[0] = 0;
}

// ---------------- fusedB: CSR fill (critical path) | GEMM0 (off-path) -----------
__global__ void __launch_bounds__(256) fusedB_kernel(
    const int* __restrict__ src, const int* __restrict__ dst, int e,
    const float* __restrict__ A, const __half* __restrict__ Wh,
    __half* __restrict__ C, int n, int FB) {
    __shared__ __half As[128][40];
    __shared__ __half Bs[128][40];
    int b = blockIdx.x;
    if (b < FB) {
        int i = b * 256 + threadIdx.x;
        if (i < e) {
            int pos = atomicAdd(&g_cur[dst[i]], 1);
            g_col[pos] = src[i];
        }
        return;
    }
    gemm_body_h<false>(As, Bs, A, nullptr, Wh, C, n, (b - FB) * 128);
}

// ---------------- GEMM layer 1 (A fp16) -----------------------------------------
__global__ void __launch_bounds__(256) gemm1_kernel(
    const __half* __restrict__ Ah, const __half* __restrict__ Wh,
    __half* __restrict__ C, int n) {
    __shared__ __half As[128][40];
    __shared__ __half Bs[128][40];
    gemm_body_h<true>(As, Bs, nullptr, Ah, Wh, C, n, blockIdx.x * 128);
}

// ---------------- gather (dinv-scaled fp16 in) + bias + PReLU + pool ------------
// out[i] = prelu(dinv[i] * (zws[i] + sum_src zws[src]) + b)
// Inner loop: int4-vectorized col loads + fp16 tree-sum per 4-edge group.
template <bool OUTHALF>
__global__ void __launch_bounds__(256) gather_kernel(
    const __half* __restrict__ zws,
    const float* __restrict__ bias,
    const float* __restrict__ alpha,
    const int* __restrict__ batch,
    void* __restrict__ zout,
    float* __restrict__ pool,
    int n, int reset) {
    __shared__ float sred[8][132];
    __shared__ int sgi[8];
    if (reset && blockIdx.x == 0 && threadIdx.x == 0) g_scan_ctr = 0;
    int wid = threadIdx.x >> 5, lane = threadIdx.x & 31;
    int i = blockIdx.x * 8 + wid;
    bool valid = i < n;

    float z0 = 0.f, z1 = 0.f, z2 = 0.f, z3 = 0.f;
    int gi = -1;

    if (valid) {
        const uint2* __restrict__ zwv = (const uint2*)zws;  // 4 halves per lane
        float di = g_dinv[i];

        uint2 sv = zwv[(size_t)i * 32 + lane];
        float2 f0 = __half22float2(*(const __half2*)&sv.x);
        float2 f1 = __half22float2(*(const __half2*)&sv.y);
        float4 acc = {f0.x, f0.y, f1.x, f1.y};

        int e0 = g_rowptr[i], e1 = g_rowptr[i + 1];
        int e = e0;
        // peel to 16B alignment of g_col
        for (; e < e1 && (e & 3); e++) {
            int s = g_col[e];
            uint2 u = zwv[(size_t)s * 32 + lane];
            float2 a = __half22float2(*(const __half2*)&u.x);
            float2 c = __half22float2(*(const __half2*)&u.y);
            acc.x += a.x; acc.y += a.y; acc.z += c.x; acc.w += c.y;
        }
        for (; e + 4 <= e1; e += 4) {
            int4 cc = *(const int4*)&g_col[e];
            uint2 u0 = zwv[(size_t)cc.x * 32 + lane];
            uint2 u1 = zwv[(size_t)cc.y * 32 + lane];
            uint2 u2 = zwv[(size_t)cc.z * 32 + lane];
            uint2 u3 = zwv[(size_t)cc.w * 32 + lane];
            // fp16 tree-sum of 4 edges (lo and hi half2 lanes)
            __half2 lo = __hadd2(
                __hadd2(*(const __half2*)&u0.x, *(const __half2*)&u1.x),
                __hadd2(*(const __half2*)&u2.x, *(const __half2*)&u3.x));
            __half2 hi = __hadd2(
                __hadd2(*(const __half2*)&u0.y, *(const __half2*)&u1.y),
                __hadd2(*(const __half2*)&u2.y, *(const __half2*)&u3.y));
            float2 flo = __half22float2(lo);
            float2 fhi = __half22float2(hi);
            acc.x += flo.x; acc.y += flo.y;
            acc.z += fhi.x; acc.w += fhi.y;
        }
        for (; e < e1; e++) {
            int s = g_col[e];
            uint2 u = zwv[(size_t)s * 32 + lane];
            float2 a = __half22float2(*(const __half2*)&u.x);
            float2 c = __half22float2(*(const __half2*)&u.y);
            acc.x += a.x; acc.y += a.y; acc.z += c.x; acc.w += c.y;
        }

        float4 b  = ((const float4*)bias)[lane];
        float4 al = ((const float4*)alpha)[lane];
        z0 = fmaf(acc.x, di, b.x);
        z1 = fmaf(acc.y, di, b.y);
        z2 = fmaf(acc.z, di, b.z);
        z3 = fmaf(acc.w, di, b.w);
        z0 = z0 > 0.0f ? z0 : al.x * z0;
        z1 = z1 > 0.0f ? z1 : al.y * z1;
        z2 = z2 > 0.0f ? z2 : al.z * z2;
        z3 = z3 > 0.0f ? z3 : al.w * z3;

        if (OUTHALF) {
            __half2 h[2];
            h[0] = __floats2half2_rn(z0, z1);
            h[1] = __floats2half2_rn(z2, z3);
            ((uint2*)zout)[(size_t)i * 32 + lane] = *(uint2*)h;
        } else {
            float4 out = {z0, z1, z2, z3};
            ((float4*)zout)[(size_t)i * 32 + lane] = out;
        }
        gi = batch[i];
    }

    if (lane == 0) sgi[wid] = gi;
    sred[wid][lane * 4 + 0] = z0;
    sred[wid][lane * 4 + 1] = z1;
    sred[wid][lane * 4 + 2] = z2;
    sred[wid][lane * 4 + 3] = z3;
    __syncthreads();

    int g0 = sgi[0];
    bool uni = (g0 >= 0);
    #pragma unroll
    for (int w = 1; w < 8; w++) uni = uni && (sgi[w] == g0);

    if (uni) {
        int f = threadIdx.x;
        if (f < 128) {
            float s = 0.f;
            #pragma unroll
            for (int w = 0; w < 8; w++) s += sred[w][f];
            atomicAdd(&pool[(size_t)g0 * 256 + f], s);
        }
    } else if (valid) {
        float* p = &pool[(size_t)gi * 256 + lane * 4];
        atomicAdd(p + 0, z0);
        atomicAdd(p + 1, z1);
        atomicAdd(p + 2, z2);
        atomicAdd(p + 3, z3);
    }
}

// ---------------- launch ----------------------------------------------------------
extern "C" void kernel_launch(void* const* d_in, const int* in_sizes, int n_in,
                              void* d_out, int out_size) {
    const float* x      = (const float*)d_in[0];
    const int*   eidx   = (const int*)d_in[1];
    const int*   batch  = (const int*)d_in[2];
    const float* W0     = (const float*)d_in[3];
    const float* b0     = (const float*)d_in[4];
    const float* alpha0 = (const float*)d_in[5];
    const float* W1     = (const float*)d_in[6];
    const float* b1     = (const float*)d_in[7];
    const float* alpha1 = (const float*)d_in[8];

    int n = in_sizes[0] / HH;       // 50000
    int e = in_sizes[1] / 2;        // 800000
    const int* src = eidx;
    const int* dst = eidx + e;

    float* z2_out = (float*)d_out;                   // [n,128]
    float* g_pool = (float*)d_out + (size_t)n * HH;  // [G, 256]
    int gsize = out_size - n * HH;                   // 65536

    __half* zwh;  cudaGetSymbolAddress((void**)&zwh, g_zwh);
    __half* z1h;  cudaGetSymbolAddress((void**)&z1h, g_z1h);
    __half* W0h;  cudaGetSymbolAddress((void**)&W0h, g_W0h);
    __half* W1h;  cudaGetSymbolAddress((void**)&W1h, g_W1h);

    int nb = (n + SCHUNK - 1) / SCHUNK;          // 98
    int GB = (n + 127) / 128;                    // 391
    int CB = (e + 255) / 256;                    // 3125
    int PB = 64;                                 // W prep blocks
    int ZB = (gsize + 255) / 256;                // 256
    int FB = CB;
    int gather_blocks = (n + 7) / 8;

    // Phase A: degree count + W fp16 transpose + pool zero (all independent)
    fusedA_kernel<<<CB + PB + ZB, 256>>>(dst, e, g_pool, gsize, W0, W1, CB, PB);

    // CSR offsets + dinv
    scan_all_kernel<<<nb, 256>>>(n, nb);

    // Phase B: CSR fill (critical path) + GEMM0 (hidden behind fill)
    fusedB_kernel<<<FB + GB, 256>>>(src, dst, e, x, W0h, zwh, n, FB);

    // Layer 0 aggregate (also resets scan counter); writes z1 as fp16
    gather_kernel<true><<<gather_blocks, 256>>>(
        zwh, b0, alpha0, batch, z1h, g_pool, n, 1);
    // Layer 1
    gemm1_kernel<<<GB, 256>>>(z1h, W1h, zwh, n);
    gather_kernel<false><<<gather_blocks, 256>>>(
        zwh, b1, alpha1, batch, z2_out, g_pool + HH, n, 0);
}

// round 12
// speedup vs baseline: 2.0724x; 1.0179x over previous
#include <cuda_runtime.h>
#include <cuda_fp16.h>
#include <cstdint>

#define NN 50000
#define EE 800000
#define HH 128
#define GG 256
#define SCHUNK 512
#define MAXNB 128   // >= ceil(NN/SCHUNK)=98

// ---------------- scratch (device globals: no allocation allowed) -----------
// 16B alignment on everything touched by vector loads (R10/R11 lesson:
// placement shifts between builds; shared arrays need it too — see kernels).
__device__ __align__(16) __half g_zwh[NN * HH];   // dinv-scaled z @ W (fp16)
__device__ __align__(16) __half g_z1h[NN * HH];   // layer-1 activation (fp16)
__device__ __align__(16) __half g_W0h[HH * HH];   // W0 transposed [n][k] fp16
__device__ __align__(16) __half g_W1h[HH * HH];   // W1 transposed [n][k] fp16
__device__ __align__(16) float g_dinv[NN];        // 1/sqrt(deg)
__device__ __align__(16) int   g_cnt[NN];         // degree histogram (0 at launch entry)
__device__ __align__(16) int   g_cur[NN];         // fill cursor
__device__ __align__(16) int   g_rowptr[NN + 1];  // CSR row pointers (by dst)
__device__ __align__(16) int   g_col[EE];         // CSR column (src) — int4-read!
__device__ __align__(16) int   g_bsum[MAXNB];     // per-chunk sums
__device__ int   g_scan_ctr;        // scan-internal barrier (0 at launch entry)
__device__ int   g_scan_done;       // scan-complete counter (0 at launch entry)

// ---------------- fp16 MMA helper ----------------------------------------------
__device__ __forceinline__ void mma_f16(float c[4],
                                        uint32_t a0, uint32_t a1,
                                        uint32_t a2, uint32_t a3,
                                        uint32_t b0, uint32_t b1) {
    asm volatile(
        "mma.sync.aligned.m16n8k16.row.col.f32.f16.f16.f32 "
        "{%0,%1,%2,%3}, {%4,%5,%6,%7}, {%8,%9}, {%0,%1,%2,%3};"
        : "+f"(c[0]), "+f"(c[1]), "+f"(c[2]), "+f"(c[3])
        : "r"(a0), "r"(a1), "r"(a2), "r"(a3), "r"(b0), "r"(b1));
}

// ---------------- fp16 GEMM body: C[r] = dinv[r] * (A[r,:] @ W)  ----------------
template <bool AHALF>
__device__ __forceinline__ void gemm_body_h(
    __half (*As)[40], __half (*Bs)[40],
    const float* __restrict__ Af, const __half* __restrict__ Ah,
    const __half* __restrict__ Wh,
    __half* __restrict__ C, int n, int m0) {
    int tid = threadIdx.x;
    int lane = tid & 31, wid = tid >> 5;
    int wm = wid >> 1;
    int wn = wid & 1;

    float acc[2][8][4];
    #pragma unroll
    for (int ms = 0; ms < 2; ms++)
        #pragma unroll
        for (int nt = 0; nt < 8; nt++)
            #pragma unroll
            for (int j = 0; j < 4; j++) acc[ms][nt][j] = 0.0f;

    int rq = lane >> 2;
    int kq = (lane & 3) * 2;

    for (int k0 = 0; k0 < 128; k0 += 32) {
        #pragma unroll
        for (int it = 0; it < 2; it++) {
            int f = tid + 256 * it;
            int row = f >> 2;
            int k8 = (f & 3) * 8;
            int rg = m0 + row;
            if (rg >= n) rg = n - 1;
            if (AHALF) {
                uint4 v = *(const uint4*)&Ah[(size_t)rg * 128 + k0 + k8];
                *(uint4*)&As[row][k8] = v;
            } else {
                float4 a0 = *(const float4*)&Af[(size_t)rg * 128 + k0 + k8];
                float4 a1 = *(const float4*)&Af[(size_t)rg * 128 + k0 + k8 + 4];
                __half2 h[4];
                h[0] = __floats2half2_rn(a0.x, a0.y);
                h[1] = __floats2half2_rn(a0.z, a0.w);
                h[2] = __floats2half2_rn(a1.x, a1.y);
                h[3] = __floats2half2_rn(a1.z, a1.w);
                *(uint4*)&As[row][k8] = *(uint4*)h;
            }
        }
        #pragma unroll
        for (int it = 0; it < 2; it++) {
            int f = tid + 256 * it;
            int nr = f >> 2;
            int k8 = (f & 3) * 8;
            uint4 v = *(const uint4*)&Wh[(size_t)nr * 128 + k0 + k8];
            *(uint4*)&Bs[nr][k8] = v;
        }
        __syncthreads();

        #pragma unroll
        for (int kk = 0; kk < 32; kk += 16) {
            uint32_t a[2][4];
            #pragma unroll
            for (int ms = 0; ms < 2; ms++) {
                int r = wm * 32 + ms * 16 + rq;
                a[ms][0] = *(const uint32_t*)&As[r][kk + kq];
                a[ms][1] = *(const uint32_t*)&As[r + 8][kk + kq];
                a[ms][2] = *(const uint32_t*)&As[r][kk + kq + 8];
                a[ms][3] = *(const uint32_t*)&As[r + 8][kk + kq + 8];
            }
            #pragma unroll
            for (int nt = 0; nt < 8; nt++) {
                int nc = wn * 64 + nt * 8 + rq;
                uint32_t b0 = *(const uint32_t*)&Bs[nc][kk + kq];
                uint32_t b1 = *(const uint32_t*)&Bs[nc][kk + kq + 8];
                #pragma unroll
                for (int ms = 0; ms < 2; ms++)
                    mma_f16(acc[ms][nt], a[ms][0], a[ms][1], a[ms][2], a[ms][3], b0, b1);
            }
        }
        __syncthreads();
    }

    __half2* Ch = (__half2*)C;
    #pragma unroll
    for (int ms = 0; ms < 2; ms++) {
        int r0 = m0 + wm * 32 + ms * 16 + rq;
        float di0 = (r0 < n) ? g_dinv[r0] : 0.0f;
        float di8 = (r0 + 8 < n) ? g_dinv[r0 + 8] : 0.0f;
        #pragma unroll
        for (int nt = 0; nt < 8; nt++) {
            int nc = wn * 64 + nt * 8 + (lane & 3) * 2;
            if (r0 < n)
                Ch[(size_t)r0 * 64 + (nc >> 1)] =
                    __floats2half2_rn(di0 * acc[ms][nt][0], di0 * acc[ms][nt][1]);
            if (r0 + 8 < n)
                Ch[(size_t)(r0 + 8) * 64 + (nc >> 1)] =
                    __floats2half2_rn(di8 * acc[ms][nt][2], di8 * acc[ms][nt][3]);
        }
    }
}

// ---------------- fusedA: count | W-prep | pool-zero -----------------------------
__global__ void __launch_bounds__(256) fusedA_kernel(
    const int* __restrict__ dst, int e,
    float* __restrict__ pool, int gsize,
    const float* __restrict__ W0, const float* __restrict__ W1,
    int CB, int PB) {
    int b = blockIdx.x;
    int tid = threadIdx.x;
    if (b < CB) {
        int i = b * 256 + tid;
        if (i < e) atomicAdd(&g_cnt[dst[i]], 1);
        return;
    }
    b -= CB;
    if (b < PB) {
        int idx = b * 256 + tid;
        int k = idx >> 7, nn = idx & 127;
        g_W0h[nn * 128 + k] = __float2half(W0[k * 128 + nn]);
        g_W1h[nn * 128 + k] = __float2half(W1[k * 128 + nn]);
        return;
    }
    b -= PB;
    int i = b * 256 + tid;
    if (i < gsize) pool[i] = 0.0f;
}

// ---------------- scan body (runs inside fusedB; 98 blocks, wave-1 resident) ----
__device__ __forceinline__ void scan_body(int n, int nb, int b) {
    __shared__ int ws[8];
    __shared__ int sadd;
    int tid = threadIdx.x;
    int lane = tid & 31, wid = tid >> 5;

    int base = b * SCHUNK + tid * 2;
    int v0 = base < n ? g_cnt[base] : 0;
    int v1 = base + 1 < n ? g_cnt[base + 1] : 0;
    int t = v0 + v1;
    int s = t;
    #pragma unroll
    for (int d = 16; d > 0; d >>= 1) s += __shfl_down_sync(0xFFFFFFFFu, s, d);
    if (lane == 0) ws[wid] = s;
    __syncthreads();
    if (tid == 0) {
        int tot = 0;
        #pragma unroll
        for (int w = 0; w < 8; w++) tot += ws[w];
        g_bsum[b] = tot;
        __threadfence();
        atomicAdd(&g_scan_ctr, 1);
        while (*(volatile int*)&g_scan_ctr < nb) __nanosleep(64);
    }
    __syncthreads();
    __threadfence();

    if (tid == 0) sadd = 0;
    __syncthreads();
    int part = 0;
    for (int j = tid; j < b; j += 256) part += g_bsum[j];
    #pragma unroll
    for (int d = 16; d > 0; d >>= 1) part += __shfl_down_sync(0xFFFFFFFFu, part, d);
    if (lane == 0 && part != 0) atomicAdd(&sadd, part);

    int x = t;
    #pragma unroll
    for (int d = 1; d < 32; d <<= 1) {
        int y = __shfl_up_sync(0xFFFFFFFFu, x, d);
        if (lane >= d) x += y;
    }
    if (lane == 31) ws[wid] = x;
    __syncthreads();
    int add = sadd;
    for (int w = 0; w < wid; w++) add += ws[w];
    int excl = x - t + add;
    if (base < n) {
        g_rowptr[base + 1] = excl + v0;
        g_cur[base] = excl;
        g_dinv[base] = rsqrtf((float)(v0 + 1));  // +1 self loop
        g_cnt[base] = 0;                         // restore invariant
    }
    if (base + 1 < n) {
        g_rowptr[base + 2] = excl + v0 + v1;
        g_cur[base + 1] = excl + v0;
        g_dinv[base + 1] = rsqrtf((float)(v1 + 1));
        g_cnt[base + 1] = 0;
    }
    if (b == 0 && tid == 0) g_rowptr[0] = 0;

    // publish completion of this block's rowptr/cur/dinv writes
    __syncthreads();
    if (tid == 0) {
        __threadfence();
        atomicAdd(&g_scan_done, 1);
    }
}

// ---------------- fusedB: scan(98) | gemm0(391) | fill(3125, waits scan) --------
__global__ void __launch_bounds__(256) fusedB_kernel(
    const int* __restrict__ src, const int* __restrict__ dst, int e,
    const float* __restrict__ A, const __half* __restrict__ Wh,
    __half* __restrict__ C, int n, int SB, int GB, int nb) {
    // __align__(16): mixed with scan_body's int shared vars, the layout engine
    // can place these at a non-16B offset -> uint4 staging faults (R10/R11 bug).
    __shared__ __align__(16) __half As[128][40];
    __shared__ __align__(16) __half Bs[128][40];
    int b = blockIdx.x;
    if (b < SB) {
        scan_body(n, nb, b);
        return;
    }
    b -= SB;
    if (b < GB) {
        gemm_body_h<false>(As, Bs, A, nullptr, Wh, C, n, b * 128);
        return;
    }
    b -= GB;
    // fill: wait for all scan blocks
    if (threadIdx.x == 0) {
        while (*(volatile int*)&g_scan_done < SB) __nanosleep(64);
    }
    __syncthreads();
    __threadfence();
    int i = b * 256 + threadIdx.x;
    if (i < e) {
        int pos = atomicAdd(&g_cur[dst[i]], 1);
        g_col[pos] = src[i];
    }
}

// ---------------- GEMM layer 1 (A fp16) -----------------------------------------
__global__ void __launch_bounds__(256) gemm1_kernel(
    const __half* __restrict__ Ah, const __half* __restrict__ Wh,
    __half* __restrict__ C, int n) {
    __shared__ __align__(16) __half As[128][40];
    __shared__ __align__(16) __half Bs[128][40];
    gemm_body_h<true>(As, Bs, nullptr, Ah, Wh, C, n, blockIdx.x * 128);
}

// ---------------- gather (dinv-scaled fp16 in) + bias + PReLU + pool ------------
template <bool OUTHALF>
__global__ void __launch_bounds__(256) gather_kernel(
    const __half* __restrict__ zws,
    const float* __restrict__ bias,
    const float* __restrict__ alpha,
    const int* __restrict__ batch,
    void* __restrict__ zout,
    float* __restrict__ pool,
    int n, int reset) {
    __shared__ float sred[8][132];
    __shared__ int sgi[8];
    if (reset && blockIdx.x == 0 && threadIdx.x == 0) {
        g_scan_ctr = 0;
        g_scan_done = 0;
    }
    int wid = threadIdx.x >> 5, lane = threadIdx.x & 31;
    int i = blockIdx.x * 8 + wid;
    bool valid = i < n;

    float z0 = 0.f, z1 = 0.f, z2 = 0.f, z3 = 0.f;
    int gi = -1;

    if (valid) {
        const uint2* __restrict__ zwv = (const uint2*)zws;  // 4 halves per lane
        float di = g_dinv[i];

        uint2 sv = zwv[(size_t)i * 32 + lane];
        float2 f0 = __half22float2(*(const __half2*)&sv.x);
        float2 f1 = __half22float2(*(const __half2*)&sv.y);
        float4 acc = {f0.x, f0.y, f1.x, f1.y};

        int e0 = g_rowptr[i], e1 = g_rowptr[i + 1];
        int e = e0;
        // peel to 16B alignment of g_col (base is __align__(16))
        for (; e < e1 && (e & 3); e++) {
            int s = g_col[e];
            uint2 u = zwv[(size_t)s * 32 + lane];
            float2 a = __half22float2(*(const __half2*)&u.x);
            float2 c = __half22float2(*(const __half2*)&u.y);
            acc.x += a.x; acc.y += a.y; acc.z += c.x; acc.w += c.y;
        }
        // 8-edge groups
        for (; e + 8 <= e1; e += 8) {
            int4 cA = *(const int4*)&g_col[e];
            int4 cB = *(const int4*)&g_col[e + 4];
            uint2 u0 = zwv[(size_t)cA.x * 32 + lane];
            uint2 u1 = zwv[(size_t)cA.y * 32 + lane];
            uint2 u2 = zwv[(size_t)cA.z * 32 + lane];
            uint2 u3 = zwv[(size_t)cA.w * 32 + lane];
            uint2 u4 = zwv[(size_t)cB.x * 32 + lane];
            uint2 u5 = zwv[(size_t)cB.y * 32 + lane];
            uint2 u6 = zwv[(size_t)cB.z * 32 + lane];
            uint2 u7 = zwv[(size_t)cB.w * 32 + lane];
            __half2 loA = __hadd2(
                __hadd2(*(const __half2*)&u0.x, *(const __half2*)&u1.x),
                __hadd2(*(const __half2*)&u2.x, *(const __half2*)&u3.x));
            __half2 hiA = __hadd2(
                __hadd2(*(const __half2*)&u0.y, *(const __half2*)&u1.y),
                __hadd2(*(const __half2*)&u2.y, *(const __half2*)&u3.y));
            __half2 loB = __hadd2(
                __hadd2(*(const __half2*)&u4.x, *(const __half2*)&u5.x),
                __hadd2(*(const __half2*)&u6.x, *(const __half2*)&u7.x));
            __half2 hiB = __hadd2(
                __hadd2(*(const __half2*)&u4.y, *(const __half2*)&u5.y),
                __hadd2(*(const __half2*)&u6.y, *(const __half2*)&u7.y));
            float2 fa = __half22float2(loA);
            float2 fb = __half22float2(hiA);
            float2 fc = __half22float2(loB);
            float2 fd = __half22float2(hiB);
            acc.x += fa.x + fc.x; acc.y += fa.y + fc.y;
            acc.z += fb.x + fd.x; acc.w += fb.y + fd.y;
        }
        // 4-edge group
        for (; e + 4 <= e1; e += 4) {
            int4 cc = *(const int4*)&g_col[e];
            uint2 u0 = zwv[(size_t)cc.x * 32 + lane];
            uint2 u1 = zwv[(size_t)cc.y * 32 + lane];
            uint2 u2 = zwv[(size_t)cc.z * 32 + lane];
            uint2 u3 = zwv[(size_t)cc.w * 32 + lane];
            __half2 lo = __hadd2(
                __hadd2(*(const __half2*)&u0.x, *(const __half2*)&u1.x),
                __hadd2(*(const __half2*)&u2.x, *(const __half2*)&u3.x));
            __half2 hi = __hadd2(
                __hadd2(*(const __half2*)&u0.y, *(const __half2*)&u1.y),
                __hadd2(*(const __half2*)&u2.y, *(const __half2*)&u3.y));
            float2 flo = __half22float2(lo);
            float2 fhi = __half22float2(hi);
            acc.x += flo.x; acc.y += flo.y;
            acc.z += fhi.x; acc.w += fhi.y;
        }
        // scalar tail
        for (; e < e1; e++) {
            int s = g_col[e];
            uint2 u = zwv[(size_t)s * 32 + lane];
            float2 a = __half22float2(*(const __half2*)&u.x);
            float2 c = __half22float2(*(const __half2*)&u.y);
            acc.x += a.x; acc.y += a.y; acc.z += c.x; acc.w += c.y;
        }

        float4 b  = ((const float4*)bias)[lane];
        float4 al = ((const float4*)alpha)[lane];
        z0 = fmaf(acc.x, di, b.x);
        z1 = fmaf(acc.y, di, b.y);
        z2 = fmaf(acc.z, di, b.z);
        z3 = fmaf(acc.w, di, b.w);
        z0 = z0 > 0.0f ? z0 : al.x * z0;
        z1 = z1 > 0.0f ? z1 : al.y * z1;
        z2 = z2 > 0.0f ? z2 : al.z * z2;
        z3 = z3 > 0.0f ? z3 : al.w * z3;

        if (OUTHALF) {
            __half2 h[2];
            h[0] = __floats2half2_rn(z0, z1);
            h[1] = __floats2half2_rn(z2, z3);
            ((uint2*)zout)[(size_t)i * 32 + lane] = *(uint2*)h;
        } else {
            float4 out = {z0, z1, z2, z3};
            ((float4*)zout)[(size_t)i * 32 + lane] = out;
        }
        gi = batch[i];
    }

    if (lane == 0) sgi[wid] = gi;
    sred[wid][lane * 4 + 0] = z0;
    sred[wid][lane * 4 + 1] = z1;
    sred[wid][lane * 4 + 2] = z2;
    sred[wid][lane * 4 + 3] = z3;
    __syncthreads();

    int g0 = sgi[0];
    bool uni = (g0 >= 0);
    #pragma unroll
    for (int w = 1; w < 8; w++) uni = uni && (sgi[w] == g0);

    if (uni) {
        int f = threadIdx.x;
        if (f < 128) {
            float s = 0.f;
            #pragma unroll
            for (int w = 0; w < 8; w++) s += sred[w][f];
            atomicAdd(&pool[(size_t)g0 * 256 + f], s);
        }
    } else if (valid) {
        float* p = &pool[(size_t)gi * 256 + lane * 4];
        atomicAdd(p + 0, z0);
        atomicAdd(p + 1, z1);
        atomicAdd(p + 2, z2);
        atomicAdd(p + 3, z3);
    }
}

// ---------------- launch ----------------------------------------------------------
extern "C" void kernel_launch(void* const* d_in, const int* in_sizes, int n_in,
                              void* d_out, int out_size) {
    const float* x      = (const float*)d_in[0];
    const int*   eidx   = (const int*)d_in[1];
    const int*   batch  = (const int*)d_in[2];
    const float* W0     = (const float*)d_in[3];
    const float* b0     = (const float*)d_in[4];
    const float* alpha0 = (const float*)d_in[5];
    const float* W1     = (const float*)d_in[6];
    const float* b1     = (const float*)d_in[7];
    const float* alpha1 = (const float*)d_in[8];

    int n = in_sizes[0] / HH;       // 50000
    int e = in_sizes[1] / 2;        // 800000
    const int* src = eidx;
    const int* dst = eidx + e;

    float* z2_out = (float*)d_out;                   // [n,128]
    float* g_pool = (float*)d_out + (size_t)n * HH;  // [G, 256]
    int gsize = out_size - n * HH;                   // 65536

    __half* zwh;  cudaGetSymbolAddress((void**)&zwh, g_zwh);
    __half* z1h;  cudaGetSymbolAddress((void**)&z1h, g_z1h);
    __half* W0h;  cudaGetSymbolAddress((void**)&W0h, g_W0h);
    __half* W1h;  cudaGetSymbolAddress((void**)&W1h, g_W1h);

    int nb = (n + SCHUNK - 1) / SCHUNK;          // 98
    int GB = (n + 127) / 128;                    // 391
    int CB = (e + 255) / 256;                    // 3125
    int PB = 64;                                 // W prep blocks
    int ZB = (gsize + 255) / 256;                // 256
    int FB = CB;
    int gather_blocks = (n + 7) / 8;

    // Phase A: degree count + W fp16 transpose + pool zero (all independent)
    fusedA_kernel<<<CB + PB + ZB, 256>>>(dst, e, g_pool, gsize, W0, W1, CB, PB);

    // Phase B: scan (wave 1) | GEMM0 (independent) | fill (waits on scan counter)
    fusedB_kernel<<<nb + GB + FB, 256>>>(src, dst, e, x, W0h, zwh, n, nb, GB, nb);

    // Layer 0 aggregate (also resets counters); writes z1 as fp16
    gather_kernel<true><<<gather_blocks, 256>>>(
        zwh, b0, alpha0, batch, z1h, g_pool, n, 1);
    // Layer 1
    gemm1_kernel<<<GB, 256>>>(z1h, W1h, zwh, n);
    gather_kernel<false><<<gather_blocks, 256>>>(
        zwh, b1, alpha1, batch, z2_out, g_pool + HH, n, 0);
}

// round 13
// speedup vs baseline: 2.1114x; 1.0188x over previous
#include <cuda_runtime.h>
#include <cuda_fp16.h>
#include <cstdint>

#define NN 50000
#define EE 800000
#define HH 128
#define GG 256
#define SCHUNK 512
#define MAXNB 128   // >= ceil(NN/SCHUNK)=98
#define FSTRIDE 136 // full-K smem row stride (halves): 68 words ≡ 4 mod 32 -> conflict-free
#define SMEM_FULL (2 * 128 * FSTRIDE * 2)  // 69632 bytes

// ---------------- scratch (device globals: no allocation allowed) -----------
__device__ __align__(16) __half g_zwh[NN * HH];   // dinv-scaled z @ W (fp16)
__device__ __align__(16) __half g_z1h[NN * HH];   // layer-1 activation (fp16)
__device__ __align__(16) __half g_W0h[HH * HH];   // W0 transposed [n][k] fp16
__device__ __align__(16) __half g_W1h[HH * HH];   // W1 transposed [n][k] fp16
__device__ __align__(16) float g_dinv[NN];        // 1/sqrt(deg)
__device__ __align__(16) int   g_cnt[NN];         // degree histogram (0 at launch entry)
__device__ __align__(16) int   g_cur[NN];         // fill cursor
__device__ __align__(16) int   g_rowptr[NN + 1];  // CSR row pointers (by dst)
__device__ __align__(16) int   g_col[EE];         // CSR column (src) — int4-read!
__device__ __align__(16) int   g_bsum[MAXNB];     // per-chunk sums
__device__ int   g_scan_ctr;        // scan-internal barrier (0 at launch entry)
__device__ int   g_scan_done;       // scan-complete counter (0 at launch entry)

// ---------------- fp16 MMA helper ----------------------------------------------
__device__ __forceinline__ void mma_f16(float c[4],
                                        uint32_t a0, uint32_t a1,
                                        uint32_t a2, uint32_t a3,
                                        uint32_t b0, uint32_t b1) {
    asm volatile(
        "mma.sync.aligned.m16n8k16.row.col.f32.f16.f16.f32 "
        "{%0,%1,%2,%3}, {%4,%5,%6,%7}, {%8,%9}, {%0,%1,%2,%3};"
        : "+f"(c[0]), "+f"(c[1]), "+f"(c[2]), "+f"(c[3])
        : "r"(a0), "r"(a1), "r"(a2), "r"(a3), "r"(b0), "r"(b1));
}

// ---------------- shared epilogue: scale by dinv, write fp16 --------------------
__device__ __forceinline__ void gemm_epilogue(
    float acc[2][8][4], __half* __restrict__ C, int n, int m0,
    int lane, int wm, int wn, int rq) {
    __half2* Ch = (__half2*)C;
    #pragma unroll
    for (int ms = 0; ms < 2; ms++) {
        int r0 = m0 + wm * 32 + ms * 16 + rq;
        float di0 = (r0 < n) ? g_dinv[r0] : 0.0f;
        float di8 = (r0 + 8 < n) ? g_dinv[r0 + 8] : 0.0f;
        #pragma unroll
        for (int nt = 0; nt < 8; nt++) {
            int nc = wn * 64 + nt * 8 + (lane & 3) * 2;
            if (r0 < n)
                Ch[(size_t)r0 * 64 + (nc >> 1)] =
                    __floats2half2_rn(di0 * acc[ms][nt][0], di0 * acc[ms][nt][1]);
            if (r0 + 8 < n)
                Ch[(size_t)(r0 + 8) * 64 + (nc >> 1)] =
                    __floats2half2_rn(di8 * acc[ms][nt][2], di8 * acc[ms][nt][3]);
        }
    }
}

// ---------------- chunked fp16 GEMM body (used by fusedB / gemm0) ---------------
__device__ __forceinline__ void gemm_body_chunked(
    __half (*As)[40], __half (*Bs)[40],
    const float* __restrict__ Af,
    const __half* __restrict__ Wh,
    __half* __restrict__ C, int n, int m0) {
    int tid = threadIdx.x;
    int lane = tid & 31, wid = tid >> 5;
    int wm = wid >> 1;
    int wn = wid & 1;

    float acc[2][8][4];
    #pragma unroll
    for (int ms = 0; ms < 2; ms++)
        #pragma unroll
        for (int nt = 0; nt < 8; nt++)
            #pragma unroll
            for (int j = 0; j < 4; j++) acc[ms][nt][j] = 0.0f;

    int rq = lane >> 2;
    int kq = (lane & 3) * 2;

    for (int k0 = 0; k0 < 128; k0 += 32) {
        #pragma unroll
        for (int it = 0; it < 2; it++) {
            int f = tid + 256 * it;
            int row = f >> 2;
            int k8 = (f & 3) * 8;
            int rg = m0 + row;
            if (rg >= n) rg = n - 1;
            float4 a0 = *(const float4*)&Af[(size_t)rg * 128 + k0 + k8];
            float4 a1 = *(const float4*)&Af[(size_t)rg * 128 + k0 + k8 + 4];
            __half2 h[4];
            h[0] = __floats2half2_rn(a0.x, a0.y);
            h[1] = __floats2half2_rn(a0.z, a0.w);
            h[2] = __floats2half2_rn(a1.x, a1.y);
            h[3] = __floats2half2_rn(a1.z, a1.w);
            *(uint4*)&As[row][k8] = *(uint4*)h;
        }
        #pragma unroll
        for (int it = 0; it < 2; it++) {
            int f = tid + 256 * it;
            int nr = f >> 2;
            int k8 = (f & 3) * 8;
            uint4 v = *(const uint4*)&Wh[(size_t)nr * 128 + k0 + k8];
            *(uint4*)&Bs[nr][k8] = v;
        }
        __syncthreads();

        #pragma unroll
        for (int kk = 0; kk < 32; kk += 16) {
            uint32_t a[2][4];
            #pragma unroll
            for (int ms = 0; ms < 2; ms++) {
                int r = wm * 32 + ms * 16 + rq;
                a[ms][0] = *(const uint32_t*)&As[r][kk + kq];
                a[ms][1] = *(const uint32_t*)&As[r + 8][kk + kq];
                a[ms][2] = *(const uint32_t*)&As[r][kk + kq + 8];
                a[ms][3] = *(const uint32_t*)&As[r + 8][kk + kq + 8];
            }
            #pragma unroll
            for (int nt = 0; nt < 8; nt++) {
                int nc = wn * 64 + nt * 8 + rq;
                uint32_t b0 = *(const uint32_t*)&Bs[nc][kk + kq];
                uint32_t b1 = *(const uint32_t*)&Bs[nc][kk + kq + 8];
                #pragma unroll
                for (int ms = 0; ms < 2; ms++)
                    mma_f16(acc[ms][nt], a[ms][0], a[ms][1], a[ms][2], a[ms][3], b0, b1);
            }
        }
        __syncthreads();
    }

    gemm_epilogue(acc, C, n, m0, lane, wm, wn, rq);
}

// ---------------- fusedA: count | W-prep | pool-zero -----------------------------
__global__ void __launch_bounds__(256) fusedA_kernel(
    const int* __restrict__ dst, int e,
    float* __restrict__ pool, int gsize,
    const float* __restrict__ W0, const float* __restrict__ W1,
    int CB, int PB) {
    int b = blockIdx.x;
    int tid = threadIdx.x;
    if (b < CB) {
        int i = b * 256 + tid;
        if (i < e) atomicAdd(&g_cnt[dst[i]], 1);
        return;
    }
    b -= CB;
    if (b < PB) {
        int idx = b * 256 + tid;
        int k = idx >> 7, nn = idx & 127;
        g_W0h[nn * 128 + k] = __float2half(W0[k * 128 + nn]);
        g_W1h[nn * 128 + k] = __float2half(W1[k * 128 + nn]);
        return;
    }
    b -= PB;
    int i = b * 256 + tid;
    if (i < gsize) pool[i] = 0.0f;
}

// ---------------- scan body (runs inside fusedB; 98 blocks, wave-1 resident) ----
__device__ __forceinline__ void scan_body(int n, int nb, int b) {
    __shared__ int ws[8];
    __shared__ int sadd;
    int tid = threadIdx.x;
    int lane = tid & 31, wid = tid >> 5;

    int base = b * SCHUNK + tid * 2;
    int v0 = base < n ? g_cnt[base] : 0;
    int v1 = base + 1 < n ? g_cnt[base + 1] : 0;
    int t = v0 + v1;
    int s = t;
    #pragma unroll
    for (int d = 16; d > 0; d >>= 1) s += __shfl_down_sync(0xFFFFFFFFu, s, d);
    if (lane == 0) ws[wid] = s;
    __syncthreads();
    if (tid == 0) {
        int tot = 0;
        #pragma unroll
        for (int w = 0; w < 8; w++) tot += ws[w];
        g_bsum[b] = tot;
        __threadfence();
        atomicAdd(&g_scan_ctr, 1);
        while (*(volatile int*)&g_scan_ctr < nb) __nanosleep(64);
    }
    __syncthreads();
    __threadfence();

    if (tid == 0) sadd = 0;
    __syncthreads();
    int part = 0;
    for (int j = tid; j < b; j += 256) part += g_bsum[j];
    #pragma unroll
    for (int d = 16; d > 0; d >>= 1) part += __shfl_down_sync(0xFFFFFFFFu, part, d);
    if (lane == 0 && part != 0) atomicAdd(&sadd, part);

    int x = t;
    #pragma unroll
    for (int d = 1; d < 32; d <<= 1) {
        int y = __shfl_up_sync(0xFFFFFFFFu, x, d);
        if (lane >= d) x += y;
    }
    if (lane == 31) ws[wid] = x;
    __syncthreads();
    int add = sadd;
    for (int w = 0; w < wid; w++) add += ws[w];
    int excl = x - t + add;
    if (base < n) {
        g_rowptr[base + 1] = excl + v0;
        g_cur[base] = excl;
        g_dinv[base] = rsqrtf((float)(v0 + 1));  // +1 self loop
        g_cnt[base] = 0;                         // restore invariant
    }
    if (base + 1 < n) {
        g_rowptr[base + 2] = excl + v0 + v1;
        g_cur[base + 1] = excl + v0;
        g_dinv[base + 1] = rsqrtf((float)(v1 + 1));
        g_cnt[base + 1] = 0;
    }
    if (b == 0 && tid == 0) g_rowptr[0] = 0;

    __syncthreads();
    if (tid == 0) {
        __threadfence();
        atomicAdd(&g_scan_done, 1);
    }
}

// ---------------- fusedB: scan(98) | gemm0(391) | fill(3125, waits scan) --------
__global__ void __launch_bounds__(256) fusedB_kernel(
    const int* __restrict__ src, const int* __restrict__ dst, int e,
    const float* __restrict__ A, const __half* __restrict__ Wh,
    __half* __restrict__ C, int n, int SB, int GB, int nb) {
    __shared__ __align__(16) __half As[128][40];
    __shared__ __align__(16) __half Bs[128][40];
    int b = blockIdx.x;
    if (b < SB) {
        scan_body(n, nb, b);
        return;
    }
    b -= SB;
    if (b < GB) {
        gemm_body_chunked(As, Bs, A, Wh, C, n, b * 128);
        return;
    }
    b -= GB;
    // fill: wait for all scan blocks
    if (threadIdx.x == 0) {
        while (*(volatile int*)&g_scan_done < SB) __nanosleep(64);
    }
    __syncthreads();
    __threadfence();
    int i = b * 256 + threadIdx.x;
    if (i < e) {
        int pos = atomicAdd(&g_cur[dst[i]], 1);
        g_col[pos] = src[i];
    }
}

// ---------------- GEMM layer 1: full-K resident tiles (dynamic smem) ------------
// Load A[128x128] + W[128x128] fp16 once (one parallel burst, one sync), then
// 512 MMAs with no intermediate syncs and no repeated W traffic.
__global__ void __launch_bounds__(256) gemm1_kernel(
    const __half* __restrict__ Ah, const __half* __restrict__ Wh,
    __half* __restrict__ C, int n) {
    extern __shared__ __align__(16) __half smem[];
    __half (*As)[FSTRIDE] = (__half(*)[FSTRIDE])smem;
    __half (*Bs)[FSTRIDE] = (__half(*)[FSTRIDE])(smem + 128 * FSTRIDE);

    int tid = threadIdx.x;
    int lane = tid & 31, wid = tid >> 5;
    int wm = wid >> 1;
    int wn = wid & 1;
    int m0 = blockIdx.x * 128;

    // stage A + B fully: 2048 uint4 each, 8 per thread
    #pragma unroll
    for (int it = 0; it < 8; it++) {
        int f = tid + 256 * it;            // 0..2047
        int row = f >> 4;
        int u = (f & 15) * 8;              // half index, multiple of 8
        int rg = m0 + row;
        if (rg >= n) rg = n - 1;
        *(uint4*)&As[row][u] = *(const uint4*)&Ah[(size_t)rg * 128 + u];
        *(uint4*)&Bs[row][u] = *(const uint4*)&Wh[(size_t)row * 128 + u];
    }
    __syncthreads();

    float acc[2][8][4];
    #pragma unroll
    for (int ms = 0; ms < 2; ms++)
        #pragma unroll
        for (int nt = 0; nt < 8; nt++)
            #pragma unroll
            for (int j = 0; j < 4; j++) acc[ms][nt][j] = 0.0f;

    int rq = lane >> 2;
    int kq = (lane & 3) * 2;

    #pragma unroll
    for (int kk = 0; kk < 128; kk += 16) {
        uint32_t a[2][4];
        #pragma unroll
        for (int ms = 0; ms < 2; ms++) {
            int r = wm * 32 + ms * 16 + rq;
            a[ms][0] = *(const uint32_t*)&As[r][kk + kq];
            a[ms][1] = *(const uint32_t*)&As[r + 8][kk + kq];
            a[ms][2] = *(const uint32_t*)&As[r][kk + kq + 8];
            a[ms][3] = *(const uint32_t*)&As[r + 8][kk + kq + 8];
        }
        #pragma unroll
        for (int nt = 0; nt < 8; nt++) {
            int nc = wn * 64 + nt * 8 + rq;
            uint32_t b0 = *(const uint32_t*)&Bs[nc][kk + kq];
            uint32_t b1 = *(const uint32_t*)&Bs[nc][kk + kq + 8];
            #pragma unroll
            for (int ms = 0; ms < 2; ms++)
                mma_f16(acc[ms][nt], a[ms][0], a[ms][1], a[ms][2], a[ms][3], b0, b1);
        }
    }

    gemm_epilogue(acc, C, n, m0, lane, wm, wn, rq);
}

// ---------------- gather (dinv-scaled fp16 in) + bias + PReLU + pool ------------
template <bool OUTHALF>
__global__ void __launch_bounds__(256) gather_kernel(
    const __half* __restrict__ zws,
    const float* __restrict__ bias,
    const float* __restrict__ alpha,
    const int* __restrict__ batch,
    void* __restrict__ zout,
    float* __restrict__ pool,
    int n, int reset) {
    __shared__ float sred[8][132];
    __shared__ int sgi[8];
    if (reset && blockIdx.x == 0 && threadIdx.x == 0) {
        g_scan_ctr = 0;
        g_scan_done = 0;
    }
    int wid = threadIdx.x >> 5, lane = threadIdx.x & 31;
    int i = blockIdx.x * 8 + wid;
    bool valid = i < n;

    float z0 = 0.f, z1 = 0.f, z2 = 0.f, z3 = 0.f;
    int gi = -1;

    if (valid) {
        const uint2* __restrict__ zwv = (const uint2*)zws;  // 4 halves per lane
        float di = g_dinv[i];

        uint2 sv = zwv[(size_t)i * 32 + lane];
        float2 f0 = __half22float2(*(const __half2*)&sv.x);
        float2 f1 = __half22float2(*(const __half2*)&sv.y);
        float4 acc = {f0.x, f0.y, f1.x, f1.y};

        int e0 = g_rowptr[i], e1 = g_rowptr[i + 1];
        int e = e0;
        for (; e < e1 && (e & 3); e++) {
            int s = g_col[e];
            uint2 u = zwv[(size_t)s * 32 + lane];
            float2 a = __half22float2(*(const __half2*)&u.x);
            float2 c = __half22float2(*(const __half2*)&u.y);
            acc.x += a.x; acc.y += a.y; acc.z += c.x; acc.w += c.y;
        }
        for (; e + 8 <= e1; e += 8) {
            int4 cA = *(const int4*)&g_col[e];
            int4 cB = *(const int4*)&g_col[e + 4];
            uint2 u0 = zwv[(size_t)cA.x * 32 + lane];
            uint2 u1 = zwv[(size_t)cA.y * 32 + lane];
            uint2 u2 = zwv[(size_t)cA.z * 32 + lane];
            uint2 u3 = zwv[(size_t)cA.w * 32 + lane];
            uint2 u4 = zwv[(size_t)cB.x * 32 + lane];
            uint2 u5 = zwv[(size_t)cB.y * 32 + lane];
            uint2 u6 = zwv[(size_t)cB.z * 32 + lane];
            uint2 u7 = zwv[(size_t)cB.w * 32 + lane];
            __half2 loA = __hadd2(
                __hadd2(*(const __half2*)&u0.x, *(const __half2*)&u1.x),
                __hadd2(*(const __half2*)&u2.x, *(const __half2*)&u3.x));
            __half2 hiA = __hadd2(
                __hadd2(*(const __half2*)&u0.y, *(const __half2*)&u1.y),
                __hadd2(*(const __half2*)&u2.y, *(const __half2*)&u3.y));
            __half2 loB = __hadd2(
                __hadd2(*(const __half2*)&u4.x, *(const __half2*)&u5.x),
                __hadd2(*(const __half2*)&u6.x, *(const __half2*)&u7.x));
            __half2 hiB = __hadd2(
                __hadd2(*(const __half2*)&u4.y, *(const __half2*)&u5.y),
                __hadd2(*(const __half2*)&u6.y, *(const __half2*)&u7.y));
            float2 fa = __half22float2(loA);
            float2 fb = __half22float2(hiA);
            float2 fc = __half22float2(loB);
            float2 fd = __half22float2(hiB);
            acc.x += fa.x + fc.x; acc.y += fa.y + fc.y;
            acc.z += fb.x + fd.x; acc.w += fb.y + fd.y;
        }
        for (; e + 4 <= e1; e += 4) {
            int4 cc = *(const int4*)&g_col[e];
            uint2 u0 = zwv[(size_t)cc.x * 32 + lane];
            uint2 u1 = zwv[(size_t)cc.y * 32 + lane];
            uint2 u2 = zwv[(size_t)cc.z * 32 + lane];
            uint2 u3 = zwv[(size_t)cc.w * 32 + lane];
            __half2 lo = __hadd2(
                __hadd2(*(const __half2*)&u0.x, *(const __half2*)&u1.x),
                __hadd2(*(const __half2*)&u2.x, *(const __half2*)&u3.x));
            __half2 hi = __hadd2(
                __hadd2(*(const __half2*)&u0.y, *(const __half2*)&u1.y),
                __hadd2(*(const __half2*)&u2.y, *(const __half2*)&u3.y));
            float2 flo = __half22float2(lo);
            float2 fhi = __half22float2(hi);
            acc.x += flo.x; acc.y += flo.y;
            acc.z += fhi.x; acc.w += fhi.y;
        }
        for (; e < e1; e++) {
            int s = g_col[e];
            uint2 u = zwv[(size_t)s * 32 + lane];
            float2 a = __half22float2(*(const __half2*)&u.x);
            float2 c = __half22float2(*(const __half2*)&u.y);
            acc.x += a.x; acc.y += a.y; acc.z += c.x; acc.w += c.y;
        }

        float4 b  = ((const float4*)bias)[lane];
        float4 al = ((const float4*)alpha)[lane];
        z0 = fmaf(acc.x, di, b.x);
        z1 = fmaf(acc.y, di, b.y);
        z2 = fmaf(acc.z, di, b.z);
        z3 = fmaf(acc.w, di, b.w);
        z0 = z0 > 0.0f ? z0 : al.x * z0;
        z1 = z1 > 0.0f ? z1 : al.y * z1;
        z2 = z2 > 0.0f ? z2 : al.z * z2;
        z3 = z3 > 0.0f ? z3 : al.w * z3;

        if (OUTHALF) {
            __half2 h[2];
            h[0] = __floats2half2_rn(z0, z1);
            h[1] = __floats2half2_rn(z2, z3);
            ((uint2*)zout)[(size_t)i * 32 + lane] = *(uint2*)h;
        } else {
            float4 out = {z0, z1, z2, z3};
            ((float4*)zout)[(size_t)i * 32 + lane] = out;
        }
        gi = batch[i];
    }

    if (lane == 0) sgi[wid] = gi;
    sred[wid][lane * 4 + 0] = z0;
    sred[wid][lane * 4 + 1] = z1;
    sred[wid][lane * 4 + 2] = z2;
    sred[wid][lane * 4 + 3] = z3;
    __syncthreads();

    int g0 = sgi[0];
    bool uni = (g0 >= 0);
    #pragma unroll
    for (int w = 1; w < 8; w++) uni = uni && (sgi[w] == g0);

    if (uni) {
        int f = threadIdx.x;
        if (f < 128) {
            float s = 0.f;
            #pragma unroll
            for (int w = 0; w < 8; w++) s += sred[w][f];
            atomicAdd(&pool[(size_t)g0 * 256 + f], s);
        }
    } else if (valid) {
        float* p = &pool[(size_t)gi * 256 + lane * 4];
        atomicAdd(p + 0, z0);
        atomicAdd(p + 1, z1);
        atomicAdd(p + 2, z2);
        atomicAdd(p + 3, z3);
    }
}

// ---------------- launch ----------------------------------------------------------
extern "C" void kernel_launch(void* const* d_in, const int* in_sizes, int n_in,
                              void* d_out, int out_size) {
    const float* x      = (const float*)d_in[0];
    const int*   eidx   = (const int*)d_in[1];
    const int*   batch  = (const int*)d_in[2];
    const float* W0     = (const float*)d_in[3];
    const float* b0     = (const float*)d_in[4];
    const float* alpha0 = (const float*)d_in[5];
    const float* W1     = (const float*)d_in[6];
    const float* b1     = (const float*)d_in[7];
    const float* alpha1 = (const float*)d_in[8];

    int n = in_sizes[0] / HH;       // 50000
    int e = in_sizes[1] / 2;        // 800000
    const int* src = eidx;
    const int* dst = eidx + e;

    float* z2_out = (float*)d_out;                   // [n,128]
    float* g_pool = (float*)d_out + (size_t)n * HH;  // [G, 256]
    int gsize = out_size - n * HH;                   // 65536

    __half* zwh;  cudaGetSymbolAddress((void**)&zwh, g_zwh);
    __half* z1h;  cudaGetSymbolAddress((void**)&z1h, g_z1h);
    __half* W0h;  cudaGetSymbolAddress((void**)&W0h, g_W0h);
    __half* W1h;  cudaGetSymbolAddress((void**)&W1h, g_W1h);

    int nb = (n + SCHUNK - 1) / SCHUNK;          // 98
    int GB = (n + 127) / 128;                    // 391
    int CB = (e + 255) / 256;                    // 3125
    int PB = 64;                                 // W prep blocks
    int ZB = (gsize + 255) / 256;                // 256
    int FB = CB;
    int gather_blocks = (n + 7) / 8;

    // allow 68KB dynamic smem for the full-K GEMM (idempotent, capture-safe)
    cudaFuncSetAttribute(gemm1_kernel,
                         cudaFuncAttributeMaxDynamicSharedMemorySize, SMEM_FULL);

    // Phase A: degree count + W fp16 transpose + pool zero (all independent)
    fusedA_kernel<<<CB + PB + ZB, 256>>>(dst, e, g_pool, gsize, W0, W1, CB, PB);

    // Phase B: scan (wave 1) | GEMM0 (independent) | fill (waits on scan counter)
    fusedB_kernel<<<nb + GB + FB, 256>>>(src, dst, e, x, W0h, zwh, n, nb, GB, nb);

    // Layer 0 aggregate (also resets counters); writes z1 as fp16
    gather_kernel<true><<<gather_blocks, 256>>>(
        zwh, b0, alpha0, batch, z1h, g_pool, n, 1);
    // Layer 1 (full-K resident GEMM)
    gemm1_kernel<<<GB, 256, SMEM_FULL>>>(z1h, W1h, zwh, n);
    gather_kernel<false><<<gather_blocks, 256>>>(
        zwh, b1, alpha1, batch, z2_out, g_pool + HH, n, 0);
}